// round 3
// baseline (speedup 1.0000x reference)
#include <cuda_runtime.h>
#include <cuda_bf16.h>
#include <cstddef>

// Problem constants (fixed by the dataset): N=4, HW=4096, C=64.
#define HW   4096
#define CDIM 64
#define SCALE 0.125f   // 1/sqrt(64)

// Scratch: E[n][q][k] = exp(scale * Q[n,q,:].K[n,k,:])   (256 MiB)
__device__ float g_E[(size_t)4 * HW * HW];
// denom[n][k] = sum_q E[n][q][k]
__device__ float g_denom[4 * HW];

__global__ void zero_denom_kernel() {
    int i = blockIdx.x * blockDim.x + threadIdx.x;
    if (i < 4 * HW) g_denom[i] = 0.0f;
}

// Phase A: 64x64 tile of E = exp(scale * Q Kt), plus column sums (over q) into g_denom.
// grid: (HW/64 k-tiles, HW/64 q-tiles, N), block: 256 (16x16, each thread 4q x 4k)
__global__ void __launch_bounds__(256) phaseA_kernel(const float* __restrict__ Q,
                                                     const float* __restrict__ K) {
    const int n  = blockIdx.z;
    const int q0 = blockIdx.y * 64;
    const int k0 = blockIdx.x * 64;
    const float* Qb = Q + ((size_t)n * HW + q0) * CDIM;
    const float* Kb = K + ((size_t)n * HW + k0) * CDIM;

    __shared__ float Qs[64][68];  // [c][q]  (transposed on load)
    __shared__ float Ks[64][68];  // [c][k]
    __shared__ float red[64];     // per-block column sums

    const int tid = threadIdx.x;
    if (tid < 64) red[tid] = 0.0f;

    // Load both 64x64 tiles (1024 float4 each), transpose into smem.
#pragma unroll
    for (int i = 0; i < 4; i++) {
        int lin = tid + i * 256;          // 0..1023
        int row = lin >> 4;               // local row (q or k)
        int c4  = (lin & 15) * 4;         // c offset
        float4 v = *(const float4*)(Qb + row * CDIM + c4);
        Qs[c4 + 0][row] = v.x; Qs[c4 + 1][row] = v.y;
        Qs[c4 + 2][row] = v.z; Qs[c4 + 3][row] = v.w;
        float4 w = *(const float4*)(Kb + row * CDIM + c4);
        Ks[c4 + 0][row] = w.x; Ks[c4 + 1][row] = w.y;
        Ks[c4 + 2][row] = w.z; Ks[c4 + 3][row] = w.w;
    }
    __syncthreads();

    const int tx = tid & 15;   // k micro-tile
    const int ty = tid >> 4;   // q micro-tile

    float acc[4][4] = {};
#pragma unroll 16
    for (int c = 0; c < 64; c++) {
        float4 qv = *(const float4*)&Qs[c][ty * 4];
        float4 kv = *(const float4*)&Ks[c][tx * 4];
        float qa[4] = {qv.x, qv.y, qv.z, qv.w};
        float ka[4] = {kv.x, kv.y, kv.z, kv.w};
#pragma unroll
        for (int i = 0; i < 4; i++)
#pragma unroll
            for (int j = 0; j < 4; j++)
                acc[i][j] += qa[i] * ka[j];
    }

    // exp, store E ([n][q][k], k contiguous), accumulate column sums over q.
    float csum[4] = {0.f, 0.f, 0.f, 0.f};
#pragma unroll
    for (int i = 0; i < 4; i++) {
        float e0 = __expf(acc[i][0] * SCALE);
        float e1 = __expf(acc[i][1] * SCALE);
        float e2 = __expf(acc[i][2] * SCALE);
        float e3 = __expf(acc[i][3] * SCALE);
        size_t off = ((size_t)n * HW + (q0 + ty * 4 + i)) * HW + (k0 + tx * 4);
        *(float4*)(g_E + off) = make_float4(e0, e1, e2, e3);
        csum[0] += e0; csum[1] += e1; csum[2] += e2; csum[3] += e3;
    }
#pragma unroll
    for (int j = 0; j < 4; j++)
        atomicAdd(&red[tx * 4 + j], csum[j]);
    __syncthreads();

    if (tid < 64)
        atomicAdd(&g_denom[n * HW + k0 + tid], red[tid]);
}

// Phase B: Out[n,q,c] = sum_k E[n,q,k] * V[n,k,c] / denom[n,k]
// grid: (HW/64 q-tiles, 1, N), block 256 (16x16, each thread 4q x 4c), k-loop inside.
__global__ void __launch_bounds__(256) phaseB_kernel(const float* __restrict__ V,
                                                     float* __restrict__ Out) {
    const int n  = blockIdx.z;
    const int q0 = blockIdx.x * 64;

    __shared__ float Es[64][68];  // [k][q] (transposed on load)
    __shared__ float Vs[64][68];  // [k][c] (pre-scaled by 1/denom)

    const int tid = threadIdx.x;
    const int tx = tid & 15;   // c micro-tile
    const int ty = tid >> 4;   // q micro-tile

    float acc[4][4] = {};

    for (int k0 = 0; k0 < HW; k0 += 64) {
#pragma unroll
        for (int i = 0; i < 4; i++) {
            int lin = tid + i * 256;
            int row = lin >> 4;           // q local (for E) / k local (for V)
            int c4  = (lin & 15) * 4;     // k local (for E) / c (for V)
            float4 v = *(const float4*)(g_E + ((size_t)n * HW + q0 + row) * HW + k0 + c4);
            Es[c4 + 0][row] = v.x; Es[c4 + 1][row] = v.y;
            Es[c4 + 2][row] = v.z; Es[c4 + 3][row] = v.w;

            float dinv = __frcp_rn(g_denom[n * HW + k0 + row]);
            float4 w = *(const float4*)(V + ((size_t)n * HW + k0 + row) * CDIM + c4);
            Vs[row][c4 + 0] = w.x * dinv; Vs[row][c4 + 1] = w.y * dinv;
            Vs[row][c4 + 2] = w.z * dinv; Vs[row][c4 + 3] = w.w * dinv;
        }
        __syncthreads();

#pragma unroll 16
        for (int kk = 0; kk < 64; kk++) {
            float4 ev = *(const float4*)&Es[kk][ty * 4];
            float4 vv = *(const float4*)&Vs[kk][tx * 4];
            float ea[4] = {ev.x, ev.y, ev.z, ev.w};
            float va[4] = {vv.x, vv.y, vv.z, vv.w};
#pragma unroll
            for (int i = 0; i < 4; i++)
#pragma unroll
                for (int j = 0; j < 4; j++)
                    acc[i][j] += ea[i] * va[j];
        }
        __syncthreads();
    }

#pragma unroll
    for (int i = 0; i < 4; i++) {
        size_t off = ((size_t)n * HW + (q0 + ty * 4 + i)) * CDIM + tx * 4;
        *(float4*)(Out + off) = make_float4(acc[i][0], acc[i][1], acc[i][2], acc[i][3]);
    }
}

extern "C" void kernel_launch(void* const* d_in, const int* in_sizes, int n_in,
                              void* d_out, int out_size) {
    const float* Q = (const float*)d_in[0];
    const float* K = (const float*)d_in[1];
    const float* V = (const float*)d_in[2];
    float* Out = (float*)d_out;

    const int N = in_sizes[0] / (HW * CDIM);  // = 4

    zero_denom_kernel<<<(4 * HW + 255) / 256, 256>>>();
    phaseA_kernel<<<dim3(HW / 64, HW / 64, N), 256>>>(Q, K);
    phaseB_kernel<<<dim3(HW / 64, 1, N), 256>>>(V, Out);
}

// round 5
// speedup vs baseline: 1.8942x; 1.8942x over previous
#include <cuda_runtime.h>
#include <cuda_bf16.h>
#include <cstdint>
#include <cstddef>

#define HW 4096
#define CD 64
#define SCALE 0.125f
#define SW(o) ((o) ^ (((o) >> 3) & 0x70))

// denom[n][k] = sum_q exp(scale * Q[n,q,:].K[n,k,:])
__device__ float g_denom[4 * HW];

__device__ __forceinline__ uint32_t smem_u32(const void* p) {
    uint32_t a;
    asm("{ .reg .u64 t; cvta.to.shared.u64 t, %1; cvt.u32.u64 %0, t; }" : "=r"(a) : "l"(p));
    return a;
}

// ldmatrix x4 from a 128B-row SW128 buffer. Covers 16 rows x 16 bf16 cols.
// Lane l supplies row (row0 + l&15), 16B chunk (kbyte + (l>>4)*16).
// Result regs: r0=rows0-7/k0-7, r1=rows8-15/k0-7, r2=rows0-7/k8-15, r3=rows8-15/k8-15
// -> exactly the A-fragment order of mma.m16n8k16; as B it is two n8 tiles:
//    tile0={r0,r2} (rows0-7), tile1={r1,r3} (rows8-15).
__device__ __forceinline__ void ld4(uint32_t r[4], uint32_t base, int row0, int kbyte) {
    int l = threadIdx.x & 31;
    uint32_t o = (uint32_t)((row0 + (l & 15)) * 128 + kbyte + ((l >> 4) << 4));
    uint32_t a = base + SW(o);
    asm volatile("ldmatrix.sync.aligned.m8n8.x4.shared.b16 {%0,%1,%2,%3}, [%4];"
                 : "=r"(r[0]), "=r"(r[1]), "=r"(r[2]), "=r"(r[3]) : "r"(a));
}

__device__ __forceinline__ void mma16816(float c[4], const uint32_t a[4], uint32_t b0, uint32_t b1) {
    asm volatile(
        "mma.sync.aligned.m16n8k16.row.col.f32.bf16.bf16.f32 "
        "{%0,%1,%2,%3}, {%4,%5,%6,%7}, {%8,%9}, {%0,%1,%2,%3};"
        : "+f"(c[0]), "+f"(c[1]), "+f"(c[2]), "+f"(c[3])
        : "r"(a[0]), "r"(a[1]), "r"(a[2]), "r"(a[3]), "r"(b0), "r"(b1));
}

// [128 rows x 64 cols] fp32 -> split bf16 hi/lo, 128B rows, SW128. 256 threads.
__device__ __forceinline__ void load_split_128x64(const float* __restrict__ g,
                                                  char* smem, int off_hi, int off_lo) {
    int tid = threadIdx.x;
#pragma unroll
    for (int i = 0; i < 8; i++) {
        int lin4 = i * 256 + tid;
        int row  = lin4 >> 4;
        int c4   = (lin4 & 15) * 4;
        float4 v = *(const float4*)(g + row * CD + c4);
        __nv_bfloat162 h0 = __floats2bfloat162_rn(v.x, v.y);
        __nv_bfloat162 h1 = __floats2bfloat162_rn(v.z, v.w);
        __nv_bfloat162 l0 = __floats2bfloat162_rn(v.x - __low2float(h0), v.y - __high2float(h0));
        __nv_bfloat162 l1 = __floats2bfloat162_rn(v.z - __low2float(h1), v.w - __high2float(h1));
        unsigned o = row * 128 + c4 * 2;
        unsigned s = SW(o);
        *(unsigned*)(smem + off_hi + s)     = *(unsigned*)&h0;
        *(unsigned*)(smem + off_hi + s + 4) = *(unsigned*)&h1;
        *(unsigned*)(smem + off_lo + s)     = *(unsigned*)&l0;
        *(unsigned*)(smem + off_lo + s + 4) = *(unsigned*)&l1;
    }
}

// V chunk [128 k x 64 c] fp32, scaled by 1/denom[k], TRANSPOSED to Vt[c][k]:
// two half-buffers (k<64 at +0, k>=64 at +8192), 64 rows(c) x 64 cols(k) each,
// split hi/lo. 256 threads.
__device__ __forceinline__ void load_vt_128x64(const float* __restrict__ g,
                                               const float* __restrict__ dn,
                                               char* smem, int off_hi, int off_lo) {
    int tid = threadIdx.x;
#pragma unroll
    for (int i = 0; i < 8; i++) {
        int lin4 = i * 256 + tid;
        int k  = lin4 >> 4;
        int c4 = (lin4 & 15) * 4;
        float di = __frcp_rn(dn[k]);
        float4 v = *(const float4*)(g + k * CD + c4);
        float vv[4] = {v.x * di, v.y * di, v.z * di, v.w * di};
        int half = k >> 6, kk = k & 63;
        int bh = off_hi + half * 8192, bl = off_lo + half * 8192;
#pragma unroll
        for (int j = 0; j < 4; j++) {
            __nv_bfloat16 hb = __float2bfloat16_rn(vv[j]);
            __nv_bfloat16 lb = __float2bfloat16_rn(vv[j] - __bfloat162float(hb));
            unsigned o = (c4 + j) * 128 + kk * 2;
            unsigned s = SW(o);
            *(__nv_bfloat16*)(smem + bh + s) = hb;
            *(__nv_bfloat16*)(smem + bl + s) = lb;
        }
    }
}

// ---------------------------------------------------------------------------
// Pass 1: denom. CTA = one k-tile (128 k rows). A = K (rows=k), B = Q chunks.
// Warp w owns k rows 16w..16w+15. Exp-sum over q accumulated in registers.
// ---------------------------------------------------------------------------
#define P1_KHI 0
#define P1_KLO 16384
#define P1_QHI 32768
#define P1_QLO 49152
#define P1_SMEM 65536

__global__ void __launch_bounds__(256, 1)
pass1_denom(const float* __restrict__ Q, const float* __restrict__ K) {
    extern __shared__ char smem[];
    uint32_t sb = smem_u32(smem);
    int tid = threadIdx.x, w = tid >> 5, l = tid & 31;
    int kt = blockIdx.x, n = blockIdx.y;

    load_split_128x64(K + ((size_t)n * HW + kt * 128) * CD, smem, P1_KHI, P1_KLO);
    __syncthreads();

    // A-fragments for this warp's 16 k rows (chunk-invariant)
    uint32_t ah[4][4], al[4][4];
#pragma unroll
    for (int ks = 0; ks < 4; ks++) {
        ld4(ah[ks], sb + P1_KHI, w * 16, ks * 32);
        ld4(al[ks], sb + P1_KLO, w * 16, ks * 32);
    }

    float ps0 = 0.f, ps1 = 0.f;
    for (int qc = 0; qc < 32; qc++) {
        __syncthreads();   // previous chunk's B-fragment reads complete
        load_split_128x64(Q + ((size_t)n * HW + qc * 128) * CD, smem, P1_QHI, P1_QLO);
        __syncthreads();

#pragma unroll
        for (int ntp = 0; ntp < 8; ntp++) {       // q-col tile pairs (2 x n8)
            float a0[4] = {}, a1[4] = {};
#pragma unroll
            for (int ks = 0; ks < 4; ks++) {
                uint32_t bh[4], bl[4];
                ld4(bh, sb + P1_QHI, ntp * 16, ks * 32);
                ld4(bl, sb + P1_QLO, ntp * 16, ks * 32);
                mma16816(a0, ah[ks], bh[0], bh[2]);
                mma16816(a1, ah[ks], bh[1], bh[3]);
                mma16816(a0, ah[ks], bl[0], bl[2]);
                mma16816(a1, ah[ks], bl[1], bl[3]);
                mma16816(a0, al[ks], bh[0], bh[2]);
                mma16816(a1, al[ks], bh[1], bh[3]);
            }
            ps0 += __expf(a0[0] * SCALE) + __expf(a0[1] * SCALE)
                 + __expf(a1[0] * SCALE) + __expf(a1[1] * SCALE);
            ps1 += __expf(a0[2] * SCALE) + __expf(a0[3] * SCALE)
                 + __expf(a1[2] * SCALE) + __expf(a1[3] * SCALE);
        }
    }

    // reduce across the 4 lanes of each row quad
    ps0 += __shfl_xor_sync(0xFFFFFFFFu, ps0, 1);
    ps0 += __shfl_xor_sync(0xFFFFFFFFu, ps0, 2);
    ps1 += __shfl_xor_sync(0xFFFFFFFFu, ps1, 1);
    ps1 += __shfl_xor_sync(0xFFFFFFFFu, ps1, 2);
    if ((l & 3) == 0) {
        int r = l >> 2;
        g_denom[n * HW + kt * 128 + w * 16 + r]     = ps0;
        g_denom[n * HW + kt * 128 + w * 16 + 8 + r] = ps1;
    }
}

// ---------------------------------------------------------------------------
// Pass 2: CTA = one q-tile (128 q rows). Loop 32 k-chunks:
//   S = Q.K^T -> exp -> split-bf16 P (warp-local rows) -> acc += P.Vt'
// ---------------------------------------------------------------------------
#define O_QHI  0
#define O_QLO  16384
#define O_KHI  32768
#define O_KLO  49152
#define O_PHI  65536     /* 2 x 16KB halves */
#define O_PLO  98304     /* 2 x 16KB halves */
#define O_VTHI 131072    /* 2 x 8KB halves */
#define O_VTLO 147456    /* 2 x 8KB halves */
#define P2_SMEM 163840

__global__ void __launch_bounds__(256, 1)
pass2_out(const float* __restrict__ Q, const float* __restrict__ K,
          const float* __restrict__ V, float* __restrict__ Out) {
    extern __shared__ char smem[];
    uint32_t sb = smem_u32(smem);
    int tid = threadIdx.x, w = tid >> 5, l = tid & 31;
    int qt = blockIdx.x, n = blockIdx.y;

    load_split_128x64(Q + ((size_t)n * HW + qt * 128) * CD, smem, O_QHI, O_QLO);

    float oacc[8][4];
#pragma unroll
    for (int i = 0; i < 8; i++)
#pragma unroll
        for (int j = 0; j < 4; j++) oacc[i][j] = 0.f;

    for (int kc = 0; kc < 32; kc++) {
        __syncthreads();   // previous chunk's K/Vt/P reads complete (also covers Q init)
        load_split_128x64(K + ((size_t)n * HW + kc * 128) * CD, smem, O_KHI, O_KLO);
        load_vt_128x64(V + ((size_t)n * HW + kc * 128) * CD,
                       g_denom + n * HW + kc * 128, smem, O_VTHI, O_VTLO);
        __syncthreads();

        // Q A-fragments (reloaded per chunk to limit register pressure)
        uint32_t qh[4][4], ql[4][4];
#pragma unroll
        for (int ks = 0; ks < 4; ks++) {
            ld4(qh[ks], sb + O_QHI, w * 16, ks * 32);
            ld4(ql[ks], sb + O_QLO, w * 16, ks * 32);
        }

        // --- S = Q.K^T, exp, split-bf16 P store (rows 16w..16w+15: warp-local) ---
#pragma unroll
        for (int ntp = 0; ntp < 8; ntp++) {       // k-col tile pairs
            float a0[4] = {}, a1[4] = {};
#pragma unroll
            for (int ks = 0; ks < 4; ks++) {
                uint32_t bh[4], bl[4];
                ld4(bh, sb + O_KHI, ntp * 16, ks * 32);
                ld4(bl, sb + O_KLO, ntp * 16, ks * 32);
                mma16816(a0, qh[ks], bh[0], bh[2]);
                mma16816(a1, qh[ks], bh[1], bh[3]);
                mma16816(a0, qh[ks], bl[0], bl[2]);
                mma16816(a1, qh[ks], bl[1], bl[3]);
                mma16816(a0, ql[ks], bh[0], bh[2]);
                mma16816(a1, ql[ks], bh[1], bh[3]);
            }
            int half = ntp >> 2;
            char* pbh = smem + O_PHI + half * 16384;
            char* pbl = smem + O_PLO + half * 16384;
            int qr0 = w * 16 + (l >> 2);
            int col0 = ((ntp * 16) & 63) + 2 * (l & 3);
            float e;
            // (a0: cols col0/col0+1) (a1: cols col0+8/+9); rows qr0 and qr0+8
#pragma unroll
            for (int t = 0; t < 4; t++) {
                const float* src = (t & 1) ? a1 : a0;
                int row = qr0 + ((t >> 1) ? 8 : 0);
                int c   = col0 + ((t & 1) ? 8 : 0);
                int i0  = (t >> 1) ? 2 : 0;
                float e0 = __expf(src[i0]     * SCALE);
                float e1 = __expf(src[i0 + 1] * SCALE);
                __nv_bfloat162 h = __floats2bfloat162_rn(e0, e1);
                __nv_bfloat162 lo = __floats2bfloat162_rn(e0 - __low2float(h),
                                                          e1 - __high2float(h));
                unsigned o = row * 128 + c * 2;
                unsigned s = SW(o);
                *(unsigned*)(pbh + s) = *(unsigned*)&h;
                *(unsigned*)(pbl + s) = *(unsigned*)&lo;
            }
            (void)e;
        }
        __syncwarp();   // P rows are warp-local: warp-level visibility suffices

        // --- P A-fragments (this warp's 16 q rows, 8 k16 steps) ---
        uint32_t ph[8][4], pl[8][4];
#pragma unroll
        for (int ks = 0; ks < 8; ks++) {
            int pb = (ks >= 4) ? 16384 : 0;
            int kb = (ks & 3) * 32;
            ld4(ph[ks], sb + O_PHI + pb, w * 16, kb);
            ld4(pl[ks], sb + O_PLO + pb, w * 16, kb);
        }

        // --- acc += P . Vt' ---
#pragma unroll
        for (int cp = 0; cp < 4; cp++) {          // c tile pairs
#pragma unroll
            for (int ks = 0; ks < 8; ks++) {
                uint32_t vh[4], vl[4];
                int off = (ks >= 4) ? 8192 : 0;
                int kb = (ks & 3) * 32;
                ld4(vh, sb + O_VTHI + off, cp * 16, kb);
                ld4(vl, sb + O_VTLO + off, cp * 16, kb);
                mma16816(oacc[2 * cp],     ph[ks], vh[0], vh[2]);
                mma16816(oacc[2 * cp + 1], ph[ks], vh[1], vh[3]);
                mma16816(oacc[2 * cp],     ph[ks], vl[0], vl[2]);
                mma16816(oacc[2 * cp + 1], ph[ks], vl[1], vl[3]);
                mma16816(oacc[2 * cp],     pl[ks], vh[0], vh[2]);
                mma16816(oacc[2 * cp + 1], pl[ks], vh[1], vh[3]);
            }
        }
    }

    // --- epilogue ---
    {
        int qr = qt * 128 + w * 16 + (l >> 2);
        float* o0 = Out + ((size_t)n * HW + qr) * CD;
        float* o1 = o0 + 8 * CD;
#pragma unroll
        for (int nt = 0; nt < 8; nt++) {
            int c0 = nt * 8 + 2 * (l & 3);
            *(float2*)(o0 + c0) = make_float2(oacc[nt][0], oacc[nt][1]);
            *(float2*)(o1 + c0) = make_float2(oacc[nt][2], oacc[nt][3]);
        }
    }
}

// ---------------------------------------------------------------------------
extern "C" void kernel_launch(void* const* d_in, const int* in_sizes, int n_in,
                              void* d_out, int out_size) {
    const float* Q = (const float*)d_in[0];
    const float* K = (const float*)d_in[1];
    const float* V = (const float*)d_in[2];
    float* Out = (float*)d_out;
    const int N = in_sizes[0] / (HW * CD);  // = 4

    cudaFuncSetAttribute(pass1_denom, cudaFuncAttributeMaxDynamicSharedMemorySize, P1_SMEM);
    cudaFuncSetAttribute(pass2_out,   cudaFuncAttributeMaxDynamicSharedMemorySize, P2_SMEM);

    pass1_denom<<<dim3(32, N), 256, P1_SMEM>>>(Q, K);
    pass2_out<<<dim3(32, N), 256, P2_SMEM>>>(Q, K, V, Out);
}

// round 6
// speedup vs baseline: 2.6878x; 1.4189x over previous
#include <cuda_runtime.h>
#include <cuda_bf16.h>
#include <cstdint>
#include <cstddef>

#define HW 4096
#define CD 64
#define SCALE 0.125f
#define SW(o) ((o) ^ (((o) >> 3) & 0x70))

// denom[n][k] = sum_q exp(scale * Q[n,q,:].K[n,k,:])
__device__ float g_denom[4 * HW];

// Pre-split bf16 images (swizzled, ready for cp.async -> ldmatrix):
// per (n, chunk): 32KB = [hi 16KB][lo 16KB], each 128 rows x 128B.
__device__ char g_Qb[(size_t)4 * 32 * 32768];
__device__ char g_Kb[(size_t)4 * 32 * 32768];
// Vt: per (n, chunk): [hi: half0 8KB, half1 8KB][lo: half0, half1]; rows=c(64), cols=k(64).
__device__ char g_Vb[(size_t)4 * 32 * 32768];

__device__ __forceinline__ uint32_t smem_u32(const void* p) {
    uint32_t a;
    asm("{ .reg .u64 t; cvta.to.shared.u64 t, %1; cvt.u32.u64 %0, t; }" : "=r"(a) : "l"(p));
    return a;
}

__device__ __forceinline__ void cpa16(uint32_t dst, const char* src) {
    asm volatile("cp.async.cg.shared.global [%0], [%1], 16;" :: "r"(dst), "l"(src) : "memory");
}
#define CP_COMMIT() asm volatile("cp.async.commit_group;" ::: "memory")
#define CP_WAIT0()  asm volatile("cp.async.wait_group 0;" ::: "memory")

// ldmatrix x4 from a 128B-row SW128 buffer: 16 rows x 16 bf16 cols.
// r0=rows0-7/k0-7, r1=rows8-15/k0-7, r2=rows0-7/k8-15, r3=rows8-15/k8-15.
__device__ __forceinline__ void ld4(uint32_t r[4], uint32_t base, int row0, int kbyte) {
    int l = threadIdx.x & 31;
    uint32_t o = (uint32_t)((row0 + (l & 15)) * 128 + kbyte + ((l >> 4) << 4));
    uint32_t a = base + SW(o);
    asm volatile("ldmatrix.sync.aligned.m8n8.x4.shared.b16 {%0,%1,%2,%3}, [%4];"
                 : "=r"(r[0]), "=r"(r[1]), "=r"(r[2]), "=r"(r[3]) : "r"(a));
}

__device__ __forceinline__ void mma16816(float c[4], const uint32_t a[4], uint32_t b0, uint32_t b1) {
    asm volatile(
        "mma.sync.aligned.m16n8k16.row.col.f32.bf16.bf16.f32 "
        "{%0,%1,%2,%3}, {%4,%5,%6,%7}, {%8,%9}, {%0,%1,%2,%3};"
        : "+f"(c[0]), "+f"(c[1]), "+f"(c[2]), "+f"(c[3])
        : "r"(a[0]), "r"(a[1]), "r"(a[2]), "r"(a[3]), "r"(b0), "r"(b1));
}

// [128 rows x 64 cols] fp32 -> split bf16 hi/lo, 128B rows, SW128. 256 threads.
__device__ __forceinline__ void load_split_128x64(const float* __restrict__ g,
                                                  char* smem, int off_hi, int off_lo) {
    int tid = threadIdx.x;
#pragma unroll
    for (int i = 0; i < 8; i++) {
        int lin4 = i * 256 + tid;
        int row  = lin4 >> 4;
        int c4   = (lin4 & 15) * 4;
        float4 v = *(const float4*)(g + row * CD + c4);
        __nv_bfloat162 h0 = __floats2bfloat162_rn(v.x, v.y);
        __nv_bfloat162 h1 = __floats2bfloat162_rn(v.z, v.w);
        __nv_bfloat162 l0 = __floats2bfloat162_rn(v.x - __low2float(h0), v.y - __high2float(h0));
        __nv_bfloat162 l1 = __floats2bfloat162_rn(v.z - __low2float(h1), v.w - __high2float(h1));
        unsigned o = row * 128 + c4 * 2;
        unsigned s = SW(o);
        *(unsigned*)(smem + off_hi + s)     = *(unsigned*)&h0;
        *(unsigned*)(smem + off_hi + s + 4) = *(unsigned*)&h1;
        *(unsigned*)(smem + off_lo + s)     = *(unsigned*)&l0;
        *(unsigned*)(smem + off_lo + s + 4) = *(unsigned*)&l1;
    }
}

// V chunk [128 k x 64 c] fp32, scaled by 1/denom[k], transposed to Vt[c][k]:
// half h (k block of 64) at +h*8192 inside each of hi/lo. 256 threads.
__device__ __forceinline__ void load_vt_128x64(const float* __restrict__ g,
                                               const float* __restrict__ dn,
                                               char* smem, int off_hi, int off_lo) {
    int tid = threadIdx.x;
#pragma unroll
    for (int i = 0; i < 8; i++) {
        int lin4 = i * 256 + tid;
        int k  = lin4 >> 4;
        int c4 = (lin4 & 15) * 4;
        float di = __frcp_rn(dn[k]);
        float4 v = *(const float4*)(g + k * CD + c4);
        float vv[4] = {v.x * di, v.y * di, v.z * di, v.w * di};
        int half = k >> 6, kk = k & 63;
        int bh = off_hi + half * 8192, bl = off_lo + half * 8192;
#pragma unroll
        for (int j = 0; j < 4; j++) {
            __nv_bfloat16 hb = __float2bfloat16_rn(vv[j]);
            __nv_bfloat16 lb = __float2bfloat16_rn(vv[j] - __bfloat162float(hb));
            unsigned o = (c4 + j) * 128 + kk * 2;
            unsigned s = SW(o);
            *(__nv_bfloat16*)(smem + bh + s) = hb;
            *(__nv_bfloat16*)(smem + bl + s) = lb;
        }
    }
}

// ---------------------------------------------------------------------------
// Pass 1: denom. CTA = one k-tile (128 k rows). A = K (rows=k), B = Q chunks.
// ---------------------------------------------------------------------------
#define P1_KHI 0
#define P1_KLO 16384
#define P1_QHI 32768
#define P1_QLO 49152
#define P1_SMEM 65536

__global__ void __launch_bounds__(256, 1)
pass1_denom(const float* __restrict__ Q, const float* __restrict__ K) {
    extern __shared__ char smem[];
    uint32_t sb = smem_u32(smem);
    int tid = threadIdx.x, w = tid >> 5, l = tid & 31;
    int kt = blockIdx.x, n = blockIdx.y;

    load_split_128x64(K + ((size_t)n * HW + kt * 128) * CD, smem, P1_KHI, P1_KLO);
    __syncthreads();

    uint32_t ah[4][4], al[4][4];
#pragma unroll
    for (int ks = 0; ks < 4; ks++) {
        ld4(ah[ks], sb + P1_KHI, w * 16, ks * 32);
        ld4(al[ks], sb + P1_KLO, w * 16, ks * 32);
    }

    float ps0 = 0.f, ps1 = 0.f;
    for (int qc = 0; qc < 32; qc++) {
        __syncthreads();
        load_split_128x64(Q + ((size_t)n * HW + qc * 128) * CD, smem, P1_QHI, P1_QLO);
        __syncthreads();

#pragma unroll
        for (int ntp = 0; ntp < 8; ntp++) {
            float a0[4] = {}, a1[4] = {};
#pragma unroll
            for (int ks = 0; ks < 4; ks++) {
                uint32_t bh[4], bl[4];
                ld4(bh, sb + P1_QHI, ntp * 16, ks * 32);
                ld4(bl, sb + P1_QLO, ntp * 16, ks * 32);
                mma16816(a0, ah[ks], bh[0], bh[2]);
                mma16816(a1, ah[ks], bh[1], bh[3]);
                mma16816(a0, ah[ks], bl[0], bl[2]);
                mma16816(a1, ah[ks], bl[1], bl[3]);
                mma16816(a0, al[ks], bh[0], bh[2]);
                mma16816(a1, al[ks], bh[1], bh[3]);
            }
            ps0 += __expf(a0[0] * SCALE) + __expf(a0[1] * SCALE)
                 + __expf(a1[0] * SCALE) + __expf(a1[1] * SCALE);
            ps1 += __expf(a0[2] * SCALE) + __expf(a0[3] * SCALE)
                 + __expf(a1[2] * SCALE) + __expf(a1[3] * SCALE);
        }
    }

    ps0 += __shfl_xor_sync(0xFFFFFFFFu, ps0, 1);
    ps0 += __shfl_xor_sync(0xFFFFFFFFu, ps0, 2);
    ps1 += __shfl_xor_sync(0xFFFFFFFFu, ps1, 1);
    ps1 += __shfl_xor_sync(0xFFFFFFFFu, ps1, 2);
    if ((l & 3) == 0) {
        int r = l >> 2;
        g_denom[n * HW + kt * 128 + w * 16 + r]     = ps0;
        g_denom[n * HW + kt * 128 + w * 16 + 8 + r] = ps1;
    }
}

// ---------------------------------------------------------------------------
// Prep: split Q/K/Vt(/denom) into swizzled bf16 gmem images. grid (32, N), 256 thr.
// ---------------------------------------------------------------------------
#define PQ_HI 0
#define PK_HI 32768
#define PV_HI 65536
#define PREP_SMEM 98304

__global__ void __launch_bounds__(256, 1)
prep_split(const float* __restrict__ Q, const float* __restrict__ K,
           const float* __restrict__ V) {
    extern __shared__ char smem[];
    int tid = threadIdx.x;
    int c = blockIdx.x, n = blockIdx.y;

    size_t goff = ((size_t)n * HW + c * 128) * CD;
    load_split_128x64(Q + goff, smem, PQ_HI, PQ_HI + 16384);
    load_split_128x64(K + goff, smem, PK_HI, PK_HI + 16384);
    load_vt_128x64(V + goff, g_denom + n * HW + c * 128, smem, PV_HI, PV_HI + 16384);
    __syncthreads();

    size_t gb = (size_t)(n * 32 + c) * 32768;
#pragma unroll
    for (int i = 0; i < 8; i++) {
        int o = (i * 256 + tid) * 16;
        *(float4*)(g_Qb + gb + o) = *(const float4*)(smem + PQ_HI + o);
        *(float4*)(g_Kb + gb + o) = *(const float4*)(smem + PK_HI + o);
        *(float4*)(g_Vb + gb + o) = *(const float4*)(smem + PV_HI + o);
    }
}

// ---------------------------------------------------------------------------
// Pass 2: CTA = 64 q rows, 128 threads (4 warps x 16 rows), 2 CTAs/SM.
// Loop 32 k-chunks: cp.async K/Vt bf16 -> S = Q.K^T -> exp in regs ->
// acc += P.Vt' with P as register A-fragments (no P smem round trip).
// ---------------------------------------------------------------------------
#define Q_HI  0        /* 8KB */
#define Q_LO  8192
#define K_HI  16384    /* 16KB */
#define K_LO  32768
#define VT_HI 49152    /* 16KB: two 8KB halves */
#define VT_LO 65536
#define P2_SMEM 81920

__global__ void __launch_bounds__(128, 2)
pass2_out(float* __restrict__ Out) {
    extern __shared__ char smem[];
    uint32_t sb = smem_u32(smem);
    int tid = threadIdx.x, w = tid >> 5, l = tid & 31;
    int qt = blockIdx.x, n = blockIdx.y;   // qt: 0..63 (64-row q tiles)

    // Q tile: rows 64*qt .. 64*qt+63 = half (qt&1) of prep chunk (qt>>1).
    {
        const char* qhi = g_Qb + (size_t)(n * 32 + (qt >> 1)) * 32768 + (qt & 1) * 8192;
        const char* qlo = qhi + 16384;
#pragma unroll
        for (int i = 0; i < 4; i++) {
            int o = (i * 128 + tid) * 16;
            cpa16(sb + Q_HI + o, qhi + o);
            cpa16(sb + Q_LO + o, qlo + o);
        }
        CP_COMMIT();
    }

    float oacc[8][4];
#pragma unroll
    for (int i = 0; i < 8; i++)
#pragma unroll
        for (int j = 0; j < 4; j++) oacc[i][j] = 0.f;

    uint32_t qh[4][4], ql[4][4];

    for (int kc = 0; kc < 32; kc++) {
        __syncthreads();   // previous chunk's ldmatrix reads complete
        {
            const char* ksrc = g_Kb + (size_t)(n * 32 + kc) * 32768;
            const char* vsrc = g_Vb + (size_t)(n * 32 + kc) * 32768;
#pragma unroll
            for (int i = 0; i < 16; i++) {
                int o = (i * 128 + tid) * 16;
                cpa16(sb + K_HI + o, ksrc + o);    // K_HI..K_LO contiguous 32KB
                cpa16(sb + VT_HI + o, vsrc + o);   // VT_HI..VT_LO contiguous 32KB
            }
            CP_COMMIT();
        }
        CP_WAIT0();
        __syncthreads();

        if (kc == 0) {
#pragma unroll
            for (int ks = 0; ks < 4; ks++) {
                ld4(qh[ks], sb + Q_HI, w * 16, ks * 32);
                ld4(ql[ks], sb + Q_LO, w * 16, ks * 32);
            }
        }

        // --- S = Q.K^T; exp; pack P A-fragments in registers ---
        uint32_t ph[8][4], pl[8][4];
#pragma unroll
        for (int ntp = 0; ntp < 8; ntp++) {       // k-col tile pairs (16 cols each)
            float a0[4] = {}, a1[4] = {};
#pragma unroll
            for (int ks = 0; ks < 4; ks++) {
                uint32_t bh[4], bl[4];
                ld4(bh, sb + K_HI, ntp * 16, ks * 32);
                ld4(bl, sb + K_LO, ntp * 16, ks * 32);
                mma16816(a0, qh[ks], bh[0], bh[2]);
                mma16816(a1, qh[ks], bh[1], bh[3]);
                mma16816(a0, qh[ks], bl[0], bl[2]);
                mma16816(a1, qh[ks], bl[1], bl[3]);
                mma16816(a0, ql[ks], bh[0], bh[2]);
                mma16816(a1, ql[ks], bh[1], bh[3]);
            }
            // C-frag (two n8 tiles) == A-frag (one k16 step):
            //   a0 regs {c0,c1,c2,c3} -> A {r0,r1}; a1 regs -> A {r2,r3}
            float e00 = __expf(a0[0] * SCALE), e01 = __expf(a0[1] * SCALE);
            float e02 = __expf(a0[2] * SCALE), e03 = __expf(a0[3] * SCALE);
            float e10 = __expf(a1[0] * SCALE), e11 = __expf(a1[1] * SCALE);
            float e12 = __expf(a1[2] * SCALE), e13 = __expf(a1[3] * SCALE);
            __nv_bfloat162 h;
            h = __floats2bfloat162_rn(e00, e01); ph[ntp][0] = *(uint32_t*)&h;
            __nv_bfloat162 t0 = __floats2bfloat162_rn(e00 - __low2float(h), e01 - __high2float(h));
            pl[ntp][0] = *(uint32_t*)&t0;
            h = __floats2bfloat162_rn(e02, e03); ph[ntp][1] = *(uint32_t*)&h;
            __nv_bfloat162 t1 = __floats2bfloat162_rn(e02 - __low2float(h), e03 - __high2float(h));
            pl[ntp][1] = *(uint32_t*)&t1;
            h = __floats2bfloat162_rn(e10, e11); ph[ntp][2] = *(uint32_t*)&h;
            __nv_bfloat162 t2 = __floats2bfloat162_rn(e10 - __low2float(h), e11 - __high2float(h));
            pl[ntp][2] = *(uint32_t*)&t2;
            h = __floats2bfloat162_rn(e12, e13); ph[ntp][3] = *(uint32_t*)&h;
            __nv_bfloat162 t3 = __floats2bfloat162_rn(e12 - __low2float(h), e13 - __high2float(h));
            pl[ntp][3] = *(uint32_t*)&t3;
        }

        // --- acc += P . Vt' ---
#pragma unroll
        for (int cp = 0; cp < 4; cp++) {          // c tile pairs
#pragma unroll
            for (int ks = 0; ks < 8; ks++) {      // k16 steps (== ntp index)
                uint32_t vh[4], vl[4];
                int off = (ks >= 4) ? 8192 : 0;
                int kb = (ks & 3) * 32;
                ld4(vh, sb + VT_HI + off, cp * 16, kb);
                ld4(vl, sb + VT_LO + off, cp * 16, kb);
                mma16816(oacc[2 * cp],     ph[ks], vh[0], vh[2]);
                mma16816(oacc[2 * cp + 1], ph[ks], vh[1], vh[3]);
                mma16816(oacc[2 * cp],     ph[ks], vl[0], vl[2]);
                mma16816(oacc[2 * cp + 1], ph[ks], vl[1], vl[3]);
                mma16816(oacc[2 * cp],     pl[ks], vh[0], vh[2]);
                mma16816(oacc[2 * cp + 1], pl[ks], vh[1], vh[3]);
            }
        }
    }

    // --- epilogue ---
    {
        int qr = qt * 64 + w * 16 + (l >> 2);
        float* o0 = Out + ((size_t)n * HW + qr) * CD;
        float* o1 = o0 + 8 * CD;
#pragma unroll
        for (int nt = 0; nt < 8; nt++) {
            int c0 = nt * 8 + 2 * (l & 3);
            *(float2*)(o0 + c0) = make_float2(oacc[nt][0], oacc[nt][1]);
            *(float2*)(o1 + c0) = make_float2(oacc[nt][2], oacc[nt][3]);
        }
    }
}

// ---------------------------------------------------------------------------
extern "C" void kernel_launch(void* const* d_in, const int* in_sizes, int n_in,
                              void* d_out, int out_size) {
    const float* Q = (const float*)d_in[0];
    const float* K = (const float*)d_in[1];
    const float* V = (const float*)d_in[2];
    float* Out = (float*)d_out;
    const int N = in_sizes[0] / (HW * CD);  // = 4

    cudaFuncSetAttribute(pass1_denom, cudaFuncAttributeMaxDynamicSharedMemorySize, P1_SMEM);
    cudaFuncSetAttribute(prep_split,  cudaFuncAttributeMaxDynamicSharedMemorySize, PREP_SMEM);
    cudaFuncSetAttribute(pass2_out,   cudaFuncAttributeMaxDynamicSharedMemorySize, P2_SMEM);

    pass1_denom<<<dim3(32, N), 256, P1_SMEM>>>(Q, K);
    prep_split<<<dim3(32, N), 256, PREP_SMEM>>>(Q, K, V);
    pass2_out<<<dim3(64, N), 128, P2_SMEM>>>(Out);
}

// round 7
// speedup vs baseline: 2.9227x; 1.0874x over previous
#include <cuda_runtime.h>
#include <cuda_bf16.h>
#include <cstdint>
#include <cstddef>

#define HW 4096
#define CD 64
#define SCALE 0.125f
#define SW(o) ((o) ^ (((o) >> 3) & 0x70))

// denom[n][k] = sum_q exp(scale * Q[n,q,:].K[n,k,:])
__device__ float g_denom[4 * HW];

// Pre-split bf16 images (swizzled, ready for cp.async -> ldmatrix):
// per (n, chunk): 32KB = [hi 16KB][lo 16KB], each 128 rows x 128B.
__device__ char g_Qb[(size_t)4 * 32 * 32768];
__device__ char g_Kb[(size_t)4 * 32 * 32768];
// Vt: per (n, chunk): [hi: half0 8KB, half1 8KB][lo: half0, half1]; rows=c(64), cols=k(64).
__device__ char g_Vb[(size_t)4 * 32 * 32768];

__device__ __forceinline__ uint32_t smem_u32(const void* p) {
    uint32_t a;
    asm("{ .reg .u64 t; cvta.to.shared.u64 t, %1; cvt.u32.u64 %0, t; }" : "=r"(a) : "l"(p));
    return a;
}

__device__ __forceinline__ void cpa16(uint32_t dst, const char* src) {
    asm volatile("cp.async.cg.shared.global [%0], [%1], 16;" :: "r"(dst), "l"(src) : "memory");
}
#define CP_COMMIT() asm volatile("cp.async.commit_group;" ::: "memory")
#define CP_WAIT0()  asm volatile("cp.async.wait_group 0;" ::: "memory")

// ldmatrix x4 from a 128B-row SW128 buffer: 16 rows x 16 bf16 cols.
__device__ __forceinline__ void ld4(uint32_t r[4], uint32_t base, int row0, int kbyte) {
    int l = threadIdx.x & 31;
    uint32_t o = (uint32_t)((row0 + (l & 15)) * 128 + kbyte + ((l >> 4) << 4));
    uint32_t a = base + SW(o);
    asm volatile("ldmatrix.sync.aligned.m8n8.x4.shared.b16 {%0,%1,%2,%3}, [%4];"
                 : "=r"(r[0]), "=r"(r[1]), "=r"(r[2]), "=r"(r[3]) : "r"(a));
}

__device__ __forceinline__ void mma16816(float c[4], const uint32_t a[4], uint32_t b0, uint32_t b1) {
    asm volatile(
        "mma.sync.aligned.m16n8k16.row.col.f32.bf16.bf16.f32 "
        "{%0,%1,%2,%3}, {%4,%5,%6,%7}, {%8,%9}, {%0,%1,%2,%3};"
        : "+f"(c[0]), "+f"(c[1]), "+f"(c[2]), "+f"(c[3])
        : "r"(a[0]), "r"(a[1]), "r"(a[2]), "r"(a[3]), "r"(b0), "r"(b1));
}

// [128 rows x 64 cols] fp32 -> split bf16 hi/lo, 128B rows, SW128. 256 threads.
__device__ __forceinline__ void load_split_128x64(const float* __restrict__ g,
                                                  char* smem, int off_hi, int off_lo) {
    int tid = threadIdx.x;
#pragma unroll
    for (int i = 0; i < 8; i++) {
        int lin4 = i * 256 + tid;
        int row  = lin4 >> 4;
        int c4   = (lin4 & 15) * 4;
        float4 v = *(const float4*)(g + row * CD + c4);
        __nv_bfloat162 h0 = __floats2bfloat162_rn(v.x, v.y);
        __nv_bfloat162 h1 = __floats2bfloat162_rn(v.z, v.w);
        __nv_bfloat162 l0 = __floats2bfloat162_rn(v.x - __low2float(h0), v.y - __high2float(h0));
        __nv_bfloat162 l1 = __floats2bfloat162_rn(v.z - __low2float(h1), v.w - __high2float(h1));
        unsigned o = row * 128 + c4 * 2;
        unsigned s = SW(o);
        *(unsigned*)(smem + off_hi + s)     = *(unsigned*)&h0;
        *(unsigned*)(smem + off_hi + s + 4) = *(unsigned*)&h1;
        *(unsigned*)(smem + off_lo + s)     = *(unsigned*)&l0;
        *(unsigned*)(smem + off_lo + s + 4) = *(unsigned*)&l1;
    }
}

// V chunk [128 k x 64 c] fp32, scaled by 1/denom[k], transposed to Vt[c][k].
__device__ __forceinline__ void load_vt_128x64(const float* __restrict__ g,
                                               const float* __restrict__ dn,
                                               char* smem, int off_hi, int off_lo) {
    int tid = threadIdx.x;
#pragma unroll
    for (int i = 0; i < 8; i++) {
        int lin4 = i * 256 + tid;
        int k  = lin4 >> 4;
        int c4 = (lin4 & 15) * 4;
        float di = __frcp_rn(dn[k]);
        float4 v = *(const float4*)(g + k * CD + c4);
        float vv[4] = {v.x * di, v.y * di, v.z * di, v.w * di};
        int half = k >> 6, kk = k & 63;
        int bh = off_hi + half * 8192, bl = off_lo + half * 8192;
#pragma unroll
        for (int j = 0; j < 4; j++) {
            __nv_bfloat16 hb = __float2bfloat16_rn(vv[j]);
            __nv_bfloat16 lb = __float2bfloat16_rn(vv[j] - __bfloat162float(hb));
            unsigned o = (c4 + j) * 128 + kk * 2;
            unsigned s = SW(o);
            *(__nv_bfloat16*)(smem + bh + s) = hb;
            *(__nv_bfloat16*)(smem + bl + s) = lb;
        }
    }
}

// ---------------------------------------------------------------------------
// Prep A: split Q/K into swizzled bf16 gmem images (no denom needed).
// ---------------------------------------------------------------------------
#define PQ_HI 0
#define PK_HI 32768
#define PREPQK_SMEM 65536

__global__ void __launch_bounds__(256, 1)
prep_qk(const float* __restrict__ Q, const float* __restrict__ K) {
    extern __shared__ char smem[];
    int tid = threadIdx.x;
    int c = blockIdx.x, n = blockIdx.y;

    size_t goff = ((size_t)n * HW + c * 128) * CD;
    load_split_128x64(Q + goff, smem, PQ_HI, PQ_HI + 16384);
    load_split_128x64(K + goff, smem, PK_HI, PK_HI + 16384);
    __syncthreads();

    size_t gb = (size_t)(n * 32 + c) * 32768;
#pragma unroll
    for (int i = 0; i < 8; i++) {
        int o = (i * 256 + tid) * 16;
        *(float4*)(g_Qb + gb + o) = *(const float4*)(smem + PQ_HI + o);
        *(float4*)(g_Kb + gb + o) = *(const float4*)(smem + PK_HI + o);
    }
}

__global__ void zero_denom_kernel() {
    int i = blockIdx.x * blockDim.x + threadIdx.x;
    if (i < 4 * HW) g_denom[i] = 0.0f;
}

// ---------------------------------------------------------------------------
// Pass 1: denom. CTA = 64 k rows x 8 q-chunks (q-range split 4 ways).
// 128 threads, 48KB smem, target 4 CTAs/SM. Partial sums via atomicAdd.
// ---------------------------------------------------------------------------
#define Z1_KHI 0        /* 8KB */
#define Z1_KLO 8192     /* 8KB */
#define Z1_QHI 16384    /* 16KB */
#define Z1_QLO 32768    /* 16KB */
#define P1_SMEM 49152

__global__ void __launch_bounds__(128, 4)
pass1_denom() {
    extern __shared__ char smem[];
    uint32_t sb = smem_u32(smem);
    int tid = threadIdx.x, w = tid >> 5, l = tid & 31;
    int kt = blockIdx.x;   // 0..63: 64-row k tile
    int qs = blockIdx.y;   // 0..3: q-chunk quarter
    int n  = blockIdx.z;

    // K half-tile (rows kt*64..kt*64+63) from prep chunk kt>>1, half kt&1.
    {
        const char* khi = g_Kb + (size_t)(n * 32 + (kt >> 1)) * 32768 + (kt & 1) * 8192;
        const char* klo = khi + 16384;
#pragma unroll
        for (int i = 0; i < 4; i++) {
            int o = (i * 128 + tid) * 16;
            cpa16(sb + Z1_KHI + o, khi + o);
            cpa16(sb + Z1_KLO + o, klo + o);
        }
        CP_COMMIT(); CP_WAIT0();
        __syncthreads();
    }

    // K A-fragments (chunk-invariant): warp w owns k rows w*16..w*16+15.
    uint32_t ah[4][4], al[4][4];
#pragma unroll
    for (int ks = 0; ks < 4; ks++) {
        ld4(ah[ks], sb + Z1_KHI, w * 16, ks * 32);
        ld4(al[ks], sb + Z1_KLO, w * 16, ks * 32);
    }

    float ps0 = 0.f, ps1 = 0.f;
    for (int qc = qs * 8; qc < qs * 8 + 8; qc++) {
        __syncthreads();   // previous chunk's B reads complete
        {
            const char* qsrc = g_Qb + (size_t)(n * 32 + qc) * 32768;  // hi+lo contiguous 32KB
#pragma unroll
            for (int i = 0; i < 16; i++) {
                int o = (i * 128 + tid) * 16;
                cpa16(sb + Z1_QHI + o, qsrc + o);
            }
            CP_COMMIT(); CP_WAIT0();
        }
        __syncthreads();

#pragma unroll
        for (int ntp = 0; ntp < 8; ntp++) {       // q-col tile pairs
            float a0[4] = {}, a1[4] = {};
#pragma unroll
            for (int ks = 0; ks < 4; ks++) {
                uint32_t bh[4], bl[4];
                ld4(bh, sb + Z1_QHI, ntp * 16, ks * 32);
                ld4(bl, sb + Z1_QLO, ntp * 16, ks * 32);
                mma16816(a0, ah[ks], bh[0], bh[2]);
                mma16816(a1, ah[ks], bh[1], bh[3]);
                mma16816(a0, ah[ks], bl[0], bl[2]);
                mma16816(a1, ah[ks], bl[1], bl[3]);
                mma16816(a0, al[ks], bh[0], bh[2]);
                mma16816(a1, al[ks], bh[1], bh[3]);
            }
            ps0 += __expf(a0[0] * SCALE) + __expf(a0[1] * SCALE)
                 + __expf(a1[0] * SCALE) + __expf(a1[1] * SCALE);
            ps1 += __expf(a0[2] * SCALE) + __expf(a0[3] * SCALE)
                 + __expf(a1[2] * SCALE) + __expf(a1[3] * SCALE);
        }
    }

    ps0 += __shfl_xor_sync(0xFFFFFFFFu, ps0, 1);
    ps0 += __shfl_xor_sync(0xFFFFFFFFu, ps0, 2);
    ps1 += __shfl_xor_sync(0xFFFFFFFFu, ps1, 1);
    ps1 += __shfl_xor_sync(0xFFFFFFFFu, ps1, 2);
    if ((l & 3) == 0) {
        int r = l >> 2;
        atomicAdd(&g_denom[n * HW + kt * 64 + w * 16 + r],     ps0);
        atomicAdd(&g_denom[n * HW + kt * 64 + w * 16 + 8 + r], ps1);
    }
}

// ---------------------------------------------------------------------------
// Prep B: split Vt (needs denom).
// ---------------------------------------------------------------------------
#define PV_HI 0
#define PREPV_SMEM 32768

__global__ void __launch_bounds__(256, 1)
prep_v(const float* __restrict__ V) {
    extern __shared__ char smem[];
    int tid = threadIdx.x;
    int c = blockIdx.x, n = blockIdx.y;

    load_vt_128x64(V + ((size_t)n * HW + c * 128) * CD,
                   g_denom + n * HW + c * 128, smem, PV_HI, PV_HI + 16384);
    __syncthreads();

    size_t gb = (size_t)(n * 32 + c) * 32768;
#pragma unroll
    for (int i = 0; i < 8; i++) {
        int o = (i * 256 + tid) * 16;
        *(float4*)(g_Vb + gb + o) = *(const float4*)(smem + PV_HI + o);
    }
}

// ---------------------------------------------------------------------------
// Pass 2: CTA = 64 q rows, 128 threads, 2 CTAs/SM. (unchanged from R6)
// ---------------------------------------------------------------------------
#define Q_HI  0        /* 8KB */
#define Q_LO  8192
#define K_HI  16384    /* 16KB */
#define K_LO  32768
#define VT_HI 49152    /* 16KB: two 8KB halves */
#define VT_LO 65536
#define P2_SMEM 81920

__global__ void __launch_bounds__(128, 2)
pass2_out(float* __restrict__ Out) {
    extern __shared__ char smem[];
    uint32_t sb = smem_u32(smem);
    int tid = threadIdx.x, w = tid >> 5, l = tid & 31;
    int qt = blockIdx.x, n = blockIdx.y;

    {
        const char* qhi = g_Qb + (size_t)(n * 32 + (qt >> 1)) * 32768 + (qt & 1) * 8192;
        const char* qlo = qhi + 16384;
#pragma unroll
        for (int i = 0; i < 4; i++) {
            int o = (i * 128 + tid) * 16;
            cpa16(sb + Q_HI + o, qhi + o);
            cpa16(sb + Q_LO + o, qlo + o);
        }
        CP_COMMIT();
    }

    float oacc[8][4];
#pragma unroll
    for (int i = 0; i < 8; i++)
#pragma unroll
        for (int j = 0; j < 4; j++) oacc[i][j] = 0.f;

    uint32_t qh[4][4], ql[4][4];

    for (int kc = 0; kc < 32; kc++) {
        __syncthreads();
        {
            const char* ksrc = g_Kb + (size_t)(n * 32 + kc) * 32768;
            const char* vsrc = g_Vb + (size_t)(n * 32 + kc) * 32768;
#pragma unroll
            for (int i = 0; i < 16; i++) {
                int o = (i * 128 + tid) * 16;
                cpa16(sb + K_HI + o, ksrc + o);
                cpa16(sb + VT_HI + o, vsrc + o);
            }
            CP_COMMIT();
        }
        CP_WAIT0();
        __syncthreads();

        if (kc == 0) {
#pragma unroll
            for (int ks = 0; ks < 4; ks++) {
                ld4(qh[ks], sb + Q_HI, w * 16, ks * 32);
                ld4(ql[ks], sb + Q_LO, w * 16, ks * 32);
            }
        }

        uint32_t ph[8][4], pl[8][4];
#pragma unroll
        for (int ntp = 0; ntp < 8; ntp++) {
            float a0[4] = {}, a1[4] = {};
#pragma unroll
            for (int ks = 0; ks < 4; ks++) {
                uint32_t bh[4], bl[4];
                ld4(bh, sb + K_HI, ntp * 16, ks * 32);
                ld4(bl, sb + K_LO, ntp * 16, ks * 32);
                mma16816(a0, qh[ks], bh[0], bh[2]);
                mma16816(a1, qh[ks], bh[1], bh[3]);
                mma16816(a0, qh[ks], bl[0], bl[2]);
                mma16816(a1, qh[ks], bl[1], bl[3]);
                mma16816(a0, ql[ks], bh[0], bh[2]);
                mma16816(a1, ql[ks], bh[1], bh[3]);
            }
            float e00 = __expf(a0[0] * SCALE), e01 = __expf(a0[1] * SCALE);
            float e02 = __expf(a0[2] * SCALE), e03 = __expf(a0[3] * SCALE);
            float e10 = __expf(a1[0] * SCALE), e11 = __expf(a1[1] * SCALE);
            float e12 = __expf(a1[2] * SCALE), e13 = __expf(a1[3] * SCALE);
            __nv_bfloat162 h;
            h = __floats2bfloat162_rn(e00, e01); ph[ntp][0] = *(uint32_t*)&h;
            __nv_bfloat162 t0 = __floats2bfloat162_rn(e00 - __low2float(h), e01 - __high2float(h));
            pl[ntp][0] = *(uint32_t*)&t0;
            h = __floats2bfloat162_rn(e02, e03); ph[ntp][1] = *(uint32_t*)&h;
            __nv_bfloat162 t1 = __floats2bfloat162_rn(e02 - __low2float(h), e03 - __high2float(h));
            pl[ntp][1] = *(uint32_t*)&t1;
            h = __floats2bfloat162_rn(e10, e11); ph[ntp][2] = *(uint32_t*)&h;
            __nv_bfloat162 t2 = __floats2bfloat162_rn(e10 - __low2float(h), e11 - __high2float(h));
            pl[ntp][2] = *(uint32_t*)&t2;
            h = __floats2bfloat162_rn(e12, e13); ph[ntp][3] = *(uint32_t*)&h;
            __nv_bfloat162 t3 = __floats2bfloat162_rn(e12 - __low2float(h), e13 - __high2float(h));
            pl[ntp][3] = *(uint32_t*)&t3;
        }

#pragma unroll
        for (int cp = 0; cp < 4; cp++) {
#pragma unroll
            for (int ks = 0; ks < 8; ks++) {
                uint32_t vh[4], vl[4];
                int off = (ks >= 4) ? 8192 : 0;
                int kb = (ks & 3) * 32;
                ld4(vh, sb + VT_HI + off, cp * 16, kb);
                ld4(vl, sb + VT_LO + off, cp * 16, kb);
                mma16816(oacc[2 * cp],     ph[ks], vh[0], vh[2]);
                mma16816(oacc[2 * cp + 1], ph[ks], vh[1], vh[3]);
                mma16816(oacc[2 * cp],     ph[ks], vl[0], vl[2]);
                mma16816(oacc[2 * cp + 1], ph[ks], vl[1], vl[3]);
                mma16816(oacc[2 * cp],     pl[ks], vh[0], vh[2]);
                mma16816(oacc[2 * cp + 1], pl[ks], vh[1], vh[3]);
            }
        }
    }

    {
        int qr = qt * 64 + w * 16 + (l >> 2);
        float* o0 = Out + ((size_t)n * HW + qr) * CD;
        float* o1 = o0 + 8 * CD;
#pragma unroll
        for (int nt = 0; nt < 8; nt++) {
            int c0 = nt * 8 + 2 * (l & 3);
            *(float2*)(o0 + c0) = make_float2(oacc[nt][0], oacc[nt][1]);
            *(float2*)(o1 + c0) = make_float2(oacc[nt][2], oacc[nt][3]);
        }
    }
}

// ---------------------------------------------------------------------------
extern "C" void kernel_launch(void* const* d_in, const int* in_sizes, int n_in,
                              void* d_out, int out_size) {
    const float* Q = (const float*)d_in[0];
    const float* K = (const float*)d_in[1];
    const float* V = (const float*)d_in[2];
    float* Out = (float*)d_out;
    const int N = in_sizes[0] / (HW * CD);  // = 4

    cudaFuncSetAttribute(prep_qk,     cudaFuncAttributeMaxDynamicSharedMemorySize, PREPQK_SMEM);
    cudaFuncSetAttribute(pass1_denom, cudaFuncAttributeMaxDynamicSharedMemorySize, P1_SMEM);
    cudaFuncSetAttribute(prep_v,      cudaFuncAttributeMaxDynamicSharedMemorySize, PREPV_SMEM);
    cudaFuncSetAttribute(pass2_out,   cudaFuncAttributeMaxDynamicSharedMemorySize, P2_SMEM);

    zero_denom_kernel<<<(4 * HW + 255) / 256, 256>>>();
    prep_qk<<<dim3(32, N), 256, PREPQK_SMEM>>>(Q, K);
    pass1_denom<<<dim3(64, 4, N), 128, P1_SMEM>>>();
    prep_v<<<dim3(32, N), 256, PREPV_SMEM>>>(V);
    pass2_out<<<dim3(64, N), 128, P2_SMEM>>>(Out);
}

// round 8
// speedup vs baseline: 2.9982x; 1.0258x over previous
#include <cuda_runtime.h>
#include <cuda_bf16.h>
#include <cstdint>
#include <cstddef>

#define HW 4096
#define CD 64
#define SCALE 0.125f
#define SW(o) ((o) ^ (((o) >> 3) & 0x70))

// denom[n][k] = sum_q exp(scale * Q[n,q,:].K[n,k,:])
__device__ float g_denom[4 * HW];

// Pre-split bf16 images (swizzled, ready for cp.async -> ldmatrix):
// per (n, 128-row chunk): 32KB = [hi 16KB][lo 16KB], each 128 rows x 128B.
__device__ char g_Qb[(size_t)4 * 32 * 32768];
__device__ char g_Kb[(size_t)4 * 32 * 32768];
// Vt: per (n, chunk): hi: [k-half0 8KB][k-half1 8KB], then lo same at +16384.
__device__ char g_Vb[(size_t)4 * 32 * 32768];

__device__ __forceinline__ uint32_t smem_u32(const void* p) {
    uint32_t a;
    asm("{ .reg .u64 t; cvta.to.shared.u64 t, %1; cvt.u32.u64 %0, t; }" : "=r"(a) : "l"(p));
    return a;
}

__device__ __forceinline__ void cpa16(uint32_t dst, const char* src) {
    asm volatile("cp.async.cg.shared.global [%0], [%1], 16;" :: "r"(dst), "l"(src) : "memory");
}
#define CP_COMMIT() asm volatile("cp.async.commit_group;" ::: "memory")
#define CP_WAIT0()  asm volatile("cp.async.wait_group 0;" ::: "memory")
#define CP_WAIT1()  asm volatile("cp.async.wait_group 1;" ::: "memory")

// ldmatrix x4 from a 128B-row SW128 buffer: 16 rows x 16 bf16 cols.
__device__ __forceinline__ void ld4(uint32_t r[4], uint32_t base, int row0, int kbyte) {
    int l = threadIdx.x & 31;
    uint32_t o = (uint32_t)((row0 + (l & 15)) * 128 + kbyte + ((l >> 4) << 4));
    uint32_t a = base + SW(o);
    asm volatile("ldmatrix.sync.aligned.m8n8.x4.shared.b16 {%0,%1,%2,%3}, [%4];"
                 : "=r"(r[0]), "=r"(r[1]), "=r"(r[2]), "=r"(r[3]) : "r"(a));
}

__device__ __forceinline__ void mma16816(float c[4], const uint32_t a[4], uint32_t b0, uint32_t b1) {
    asm volatile(
        "mma.sync.aligned.m16n8k16.row.col.f32.bf16.bf16.f32 "
        "{%0,%1,%2,%3}, {%4,%5,%6,%7}, {%8,%9}, {%0,%1,%2,%3};"
        : "+f"(c[0]), "+f"(c[1]), "+f"(c[2]), "+f"(c[3])
        : "r"(a[0]), "r"(a[1]), "r"(a[2]), "r"(a[3]), "r"(b0), "r"(b1));
}

__global__ void zero_denom_kernel() {
    int i = blockIdx.x * blockDim.x + threadIdx.x;
    if (i < 4 * HW) g_denom[i] = 0.0f;
}

// ---------------------------------------------------------------------------
// Prep A: split Q/K -> swizzled bf16 gmem images, direct stores (no smem).
// grid (64 slabs, N), 128 threads; slab = 64 rows.
// ---------------------------------------------------------------------------
__global__ void __launch_bounds__(128)
prep_qk(const float* __restrict__ Q, const float* __restrict__ K) {
    int tid = threadIdx.x;
    int s = blockIdx.x, n = blockIdx.y;
    int c = s >> 1, half = s & 1;
    size_t gb = (size_t)(n * 32 + c) * 32768;
    const float* Qg = Q + ((size_t)n * HW + s * 64) * CD;
    const float* Kg = K + ((size_t)n * HW + s * 64) * CD;

#pragma unroll
    for (int i = 0; i < 8; i++) {
        int lin4 = i * 128 + tid;
        int r  = lin4 >> 4;
        int c4 = (lin4 & 15) * 4;
        unsigned o = (half * 64 + r) * 128 + c4 * 2;
        unsigned sw = SW(o);
        {
            float4 v = *(const float4*)(Qg + r * CD + c4);
            __nv_bfloat162 h0 = __floats2bfloat162_rn(v.x, v.y);
            __nv_bfloat162 h1 = __floats2bfloat162_rn(v.z, v.w);
            __nv_bfloat162 l0 = __floats2bfloat162_rn(v.x - __low2float(h0), v.y - __high2float(h0));
            __nv_bfloat162 l1 = __floats2bfloat162_rn(v.z - __low2float(h1), v.w - __high2float(h1));
            *(unsigned*)(g_Qb + gb + sw)             = *(unsigned*)&h0;
            *(unsigned*)(g_Qb + gb + sw + 4)         = *(unsigned*)&h1;
            *(unsigned*)(g_Qb + gb + 16384 + sw)     = *(unsigned*)&l0;
            *(unsigned*)(g_Qb + gb + 16384 + sw + 4) = *(unsigned*)&l1;
        }
        {
            float4 v = *(const float4*)(Kg + r * CD + c4);
            __nv_bfloat162 h0 = __floats2bfloat162_rn(v.x, v.y);
            __nv_bfloat162 h1 = __floats2bfloat162_rn(v.z, v.w);
            __nv_bfloat162 l0 = __floats2bfloat162_rn(v.x - __low2float(h0), v.y - __high2float(h0));
            __nv_bfloat162 l1 = __floats2bfloat162_rn(v.z - __low2float(h1), v.w - __high2float(h1));
            *(unsigned*)(g_Kb + gb + sw)             = *(unsigned*)&h0;
            *(unsigned*)(g_Kb + gb + sw + 4)         = *(unsigned*)&h1;
            *(unsigned*)(g_Kb + gb + 16384 + sw)     = *(unsigned*)&l0;
            *(unsigned*)(g_Kb + gb + 16384 + sw + 4) = *(unsigned*)&l1;
        }
    }
}

// ---------------------------------------------------------------------------
// Pass 1: denom. CTA = 64 k rows x quarter of q-range, double-buffered Q chunks.
// smem: K 16KB + 2 x Qchunk 16KB = 48KB; 128 threads, 4 CTAs/SM.
// ---------------------------------------------------------------------------
#define Z1_KHI 0
#define Z1_KLO 8192
#define Z1_BUF(b) (16384 + (b) * 16384)
#define P1_SMEM 49152

__device__ __forceinline__ void p1_issue_q(uint32_t sb, int b, int n, int cc) {
    int tid = threadIdx.x;
    const char* qhi = g_Qb + (size_t)(n * 32 + (cc >> 1)) * 32768 + (cc & 1) * 8192;
    const char* qlo = qhi + 16384;
    uint32_t d = sb + Z1_BUF(b);
#pragma unroll
    for (int i = 0; i < 4; i++) {
        int o = (i * 128 + tid) * 16;
        cpa16(d + o, qhi + o);
        cpa16(d + 8192 + o, qlo + o);
    }
}

__global__ void __launch_bounds__(128, 4)
pass1_denom() {
    extern __shared__ char smem[];
    uint32_t sb = smem_u32(smem);
    int tid = threadIdx.x, w = tid >> 5, l = tid & 31;
    int kt = blockIdx.x;   // 0..63: 64-row k tile
    int qs = blockIdx.y;   // 0..3: q quarter (16 chunks of 64 rows)
    int n  = blockIdx.z;

    // prologue: K tile + first Q chunk as group 0
    {
        const char* khi = g_Kb + (size_t)(n * 32 + (kt >> 1)) * 32768 + (kt & 1) * 8192;
        const char* klo = khi + 16384;
#pragma unroll
        for (int i = 0; i < 4; i++) {
            int o = (i * 128 + tid) * 16;
            cpa16(sb + Z1_KHI + o, khi + o);
            cpa16(sb + Z1_KLO + o, klo + o);
        }
        p1_issue_q(sb, 0, n, qs * 16);
        CP_COMMIT();
    }

    uint32_t ah[4][4], al[4][4];
    float ps0 = 0.f, ps1 = 0.f;

    for (int j = 0; j < 16; j++) {
        int b = j & 1;
        if (j < 15) { p1_issue_q(sb, b ^ 1, n, qs * 16 + j + 1); CP_COMMIT(); CP_WAIT1(); }
        else        { CP_WAIT0(); }
        __syncthreads();

        if (j == 0) {
#pragma unroll
            for (int ks = 0; ks < 4; ks++) {
                ld4(ah[ks], sb + Z1_KHI, w * 16, ks * 32);
                ld4(al[ks], sb + Z1_KLO, w * 16, ks * 32);
            }
        }

        uint32_t qb = sb + Z1_BUF(b);
#pragma unroll
        for (int ntp = 0; ntp < 4; ntp++) {   // q-col tile pairs within 64-row chunk
            float a0[4] = {}, a1[4] = {};
#pragma unroll
            for (int ks = 0; ks < 4; ks++) {
                uint32_t bh[4], bl[4];
                ld4(bh, qb, ntp * 16, ks * 32);
                ld4(bl, qb + 8192, ntp * 16, ks * 32);
                mma16816(a0, ah[ks], bh[0], bh[2]);
                mma16816(a1, ah[ks], bh[1], bh[3]);
                mma16816(a0, ah[ks], bl[0], bl[2]);
                mma16816(a1, ah[ks], bl[1], bl[3]);
                mma16816(a0, al[ks], bh[0], bh[2]);
                mma16816(a1, al[ks], bh[1], bh[3]);
            }
            ps0 += __expf(a0[0] * SCALE) + __expf(a0[1] * SCALE)
                 + __expf(a1[0] * SCALE) + __expf(a1[1] * SCALE);
            ps1 += __expf(a0[2] * SCALE) + __expf(a0[3] * SCALE)
                 + __expf(a1[2] * SCALE) + __expf(a1[3] * SCALE);
        }
        __syncthreads();
    }

    ps0 += __shfl_xor_sync(0xFFFFFFFFu, ps0, 1);
    ps0 += __shfl_xor_sync(0xFFFFFFFFu, ps0, 2);
    ps1 += __shfl_xor_sync(0xFFFFFFFFu, ps1, 1);
    ps1 += __shfl_xor_sync(0xFFFFFFFFu, ps1, 2);
    if ((l & 3) == 0) {
        int r = l >> 2;
        atomicAdd(&g_denom[n * HW + kt * 64 + w * 16 + r],     ps0);
        atomicAdd(&g_denom[n * HW + kt * 64 + w * 16 + 8 + r], ps1);
    }
}

// ---------------------------------------------------------------------------
// Prep B: split Vt (needs denom). smem-staged (transpose), as R7.
// ---------------------------------------------------------------------------
#define PREPV_SMEM 32768

__global__ void __launch_bounds__(256, 1)
prep_v(const float* __restrict__ V) {
    extern __shared__ char smem[];
    int tid = threadIdx.x;
    int c = blockIdx.x, n = blockIdx.y;

    const float* g = V + ((size_t)n * HW + c * 128) * CD;
    const float* dn = g_denom + n * HW + c * 128;
#pragma unroll
    for (int i = 0; i < 8; i++) {
        int lin4 = i * 256 + tid;
        int k  = lin4 >> 4;
        int c4 = (lin4 & 15) * 4;
        float di = __frcp_rn(dn[k]);
        float4 v = *(const float4*)(g + k * CD + c4);
        float vv[4] = {v.x * di, v.y * di, v.z * di, v.w * di};
        int half = k >> 6, kk = k & 63;
        char* bh = smem + half * 8192;
        char* bl = smem + 16384 + half * 8192;
#pragma unroll
        for (int j = 0; j < 4; j++) {
            __nv_bfloat16 hb = __float2bfloat16_rn(vv[j]);
            __nv_bfloat16 lb = __float2bfloat16_rn(vv[j] - __bfloat162float(hb));
            unsigned o = (c4 + j) * 128 + kk * 2;
            unsigned s = SW(o);
            *(__nv_bfloat16*)(bh + s) = hb;
            *(__nv_bfloat16*)(bl + s) = lb;
        }
    }
    __syncthreads();

    size_t gb = (size_t)(n * 32 + c) * 32768;
#pragma unroll
    for (int i = 0; i < 8; i++) {
        int o = (i * 256 + tid) * 16;
        *(float4*)(g_Vb + gb + o) = *(const float4*)(smem + o);
    }
}

// ---------------------------------------------------------------------------
// Pass 2: CTA = 64 q rows, 128 threads, 2 CTAs/SM. 64 k-chunks of 64 rows,
// double-buffered K+Vt with cp.async prefetch.
// smem: Q 16KB + 2 x (K 16KB + Vt 16KB) = 80KB.
// ---------------------------------------------------------------------------
#define Q_HI 0
#define Q_LO 8192
#define BUF(b) (16384 + (b) * 32768)   /* KH, KL=+8192, VH=+16384, VL=+24576 */
#define P2_SMEM 81920

__device__ __forceinline__ void p2_issue_kv(uint32_t sb, int b, int n, int cc) {
    int tid = threadIdx.x;
    size_t cb = (size_t)(n * 32 + (cc >> 1)) * 32768 + (cc & 1) * 8192;
    const char* khi = g_Kb + cb;
    const char* vhi = g_Vb + cb;
    uint32_t d = sb + BUF(b);
#pragma unroll
    for (int i = 0; i < 4; i++) {
        int o = (i * 128 + tid) * 16;
        cpa16(d + o,         khi + o);
        cpa16(d + 8192 + o,  khi + 16384 + o);
        cpa16(d + 16384 + o, vhi + o);
        cpa16(d + 24576 + o, vhi + 16384 + o);
    }
}

__global__ void __launch_bounds__(128, 2)
pass2_out(float* __restrict__ Out) {
    extern __shared__ char smem[];
    uint32_t sb = smem_u32(smem);
    int tid = threadIdx.x, w = tid >> 5, l = tid & 31;
    int qt = blockIdx.x, n = blockIdx.y;

    // prologue: Q tile + chunk 0 as group 0
    {
        const char* qhi = g_Qb + (size_t)(n * 32 + (qt >> 1)) * 32768 + (qt & 1) * 8192;
        const char* qlo = qhi + 16384;
#pragma unroll
        for (int i = 0; i < 4; i++) {
            int o = (i * 128 + tid) * 16;
            cpa16(sb + Q_HI + o, qhi + o);
            cpa16(sb + Q_LO + o, qlo + o);
        }
        p2_issue_kv(sb, 0, n, 0);
        CP_COMMIT();
    }

    float oacc[8][4];
#pragma unroll
    for (int i = 0; i < 8; i++)
#pragma unroll
        for (int j = 0; j < 4; j++) oacc[i][j] = 0.f;

    uint32_t qh[4][4], ql[4][4];

    for (int cc = 0; cc < 64; cc++) {
        int b = cc & 1;
        if (cc < 63) { p2_issue_kv(sb, b ^ 1, n, cc + 1); CP_COMMIT(); CP_WAIT1(); }
        else         { CP_WAIT0(); }
        __syncthreads();

        if (cc == 0) {
#pragma unroll
            for (int ks = 0; ks < 4; ks++) {
                ld4(qh[ks], sb + Q_HI, w * 16, ks * 32);
                ld4(ql[ks], sb + Q_LO, w * 16, ks * 32);
            }
        }

        uint32_t kb = sb + BUF(b);
        uint32_t vb = kb + 16384;

        // --- S = Q.K^T over 64 k cols; exp; pack P A-fragments in regs ---
        uint32_t ph[4][4], pl[4][4];
#pragma unroll
        for (int ntp = 0; ntp < 4; ntp++) {
            float a0[4] = {}, a1[4] = {};
#pragma unroll
            for (int ks = 0; ks < 4; ks++) {
                uint32_t bh[4], bl[4];
                ld4(bh, kb, ntp * 16, ks * 32);
                ld4(bl, kb + 8192, ntp * 16, ks * 32);
                mma16816(a0, qh[ks], bh[0], bh[2]);
                mma16816(a1, qh[ks], bh[1], bh[3]);
                mma16816(a0, qh[ks], bl[0], bl[2]);
                mma16816(a1, qh[ks], bl[1], bl[3]);
                mma16816(a0, ql[ks], bh[0], bh[2]);
                mma16816(a1, ql[ks], bh[1], bh[3]);
            }
            float e00 = __expf(a0[0] * SCALE), e01 = __expf(a0[1] * SCALE);
            float e02 = __expf(a0[2] * SCALE), e03 = __expf(a0[3] * SCALE);
            float e10 = __expf(a1[0] * SCALE), e11 = __expf(a1[1] * SCALE);
            float e12 = __expf(a1[2] * SCALE), e13 = __expf(a1[3] * SCALE);
            __nv_bfloat162 h;
            h = __floats2bfloat162_rn(e00, e01); ph[ntp][0] = *(uint32_t*)&h;
            __nv_bfloat162 t0 = __floats2bfloat162_rn(e00 - __low2float(h), e01 - __high2float(h));
            pl[ntp][0] = *(uint32_t*)&t0;
            h = __floats2bfloat162_rn(e02, e03); ph[ntp][1] = *(uint32_t*)&h;
            __nv_bfloat162 t1 = __floats2bfloat162_rn(e02 - __low2float(h), e03 - __high2float(h));
            pl[ntp][1] = *(uint32_t*)&t1;
            h = __floats2bfloat162_rn(e10, e11); ph[ntp][2] = *(uint32_t*)&h;
            __nv_bfloat162 t2 = __floats2bfloat162_rn(e10 - __low2float(h), e11 - __high2float(h));
            pl[ntp][2] = *(uint32_t*)&t2;
            h = __floats2bfloat162_rn(e12, e13); ph[ntp][3] = *(uint32_t*)&h;
            __nv_bfloat162 t3 = __floats2bfloat162_rn(e12 - __low2float(h), e13 - __high2float(h));
            pl[ntp][3] = *(uint32_t*)&t3;
        }

        // --- acc += P . Vt' ---
#pragma unroll
        for (int cp = 0; cp < 4; cp++) {
#pragma unroll
            for (int ks = 0; ks < 4; ks++) {
                uint32_t vh[4], vl[4];
                int kbyt = ks * 32;
                ld4(vh, vb, cp * 16, kbyt);
                ld4(vl, vb + 8192, cp * 16, kbyt);
                mma16816(oacc[2 * cp],     ph[ks], vh[0], vh[2]);
                mma16816(oacc[2 * cp + 1], ph[ks], vh[1], vh[3]);
                mma16816(oacc[2 * cp],     ph[ks], vl[0], vl[2]);
                mma16816(oacc[2 * cp + 1], ph[ks], vl[1], vl[3]);
                mma16816(oacc[2 * cp],     pl[ks], vh[0], vh[2]);
                mma16816(oacc[2 * cp + 1], pl[ks], vh[1], vh[3]);
            }
        }
        __syncthreads();
    }

    {
        int qr = qt * 64 + w * 16 + (l >> 2);
        float* o0 = Out + ((size_t)n * HW + qr) * CD;
        float* o1 = o0 + 8 * CD;
#pragma unroll
        for (int nt = 0; nt < 8; nt++) {
            int c0 = nt * 8 + 2 * (l & 3);
            *(float2*)(o0 + c0) = make_float2(oacc[nt][0], oacc[nt][1]);
            *(float2*)(o1 + c0) = make_float2(oacc[nt][2], oacc[nt][3]);
        }
    }
}

// ---------------------------------------------------------------------------
extern "C" void kernel_launch(void* const* d_in, const int* in_sizes, int n_in,
                              void* d_out, int out_size) {
    const float* Q = (const float*)d_in[0];
    const float* K = (const float*)d_in[1];
    const float* V = (const float*)d_in[2];
    float* Out = (float*)d_out;
    const int N = in_sizes[0] / (HW * CD);  // = 4

    cudaFuncSetAttribute(pass1_denom, cudaFuncAttributeMaxDynamicSharedMemorySize, P1_SMEM);
    cudaFuncSetAttribute(prep_v,      cudaFuncAttributeMaxDynamicSharedMemorySize, PREPV_SMEM);
    cudaFuncSetAttribute(pass2_out,   cudaFuncAttributeMaxDynamicSharedMemorySize, P2_SMEM);

    zero_denom_kernel<<<(4 * HW + 255) / 256, 256>>>();
    prep_qk<<<dim3(64, N), 128>>>(Q, K);
    pass1_denom<<<dim3(64, 4, N), 128, P1_SMEM>>>();
    prep_v<<<dim3(32, N), 256, PREPV_SMEM>>>(V);
    pass2_out<<<dim3(64, N), 128, P2_SMEM>>>(Out);
}

// round 9
// speedup vs baseline: 3.0191x; 1.0070x over previous
#include <cuda_runtime.h>
#include <cuda_bf16.h>
#include <cstdint>
#include <cstddef>

#define HW 4096
#define CD 64
#define SCALE 0.125f
#define SW(o) ((o) ^ (((o) >> 3) & 0x70))

// denom[n][k] = sum_q exp(scale * Q[n,q,:].K[n,k,:])
__device__ float g_denom[4 * HW];

// Pre-split bf16 images (swizzled, ready for cp.async -> ldmatrix):
// per (n, 128-row chunk): 32KB = [hi 16KB][lo 16KB], each 128 rows x 128B.
__device__ char g_Qb[(size_t)4 * 32 * 32768];
__device__ char g_Kb[(size_t)4 * 32 * 32768];
// Vt: per (n, chunk): hi: [k-half0 8KB][k-half1 8KB], then lo same at +16384.
__device__ char g_Vb[(size_t)4 * 32 * 32768];

__device__ __forceinline__ uint32_t smem_u32(const void* p) {
    uint32_t a;
    asm("{ .reg .u64 t; cvta.to.shared.u64 t, %1; cvt.u32.u64 %0, t; }" : "=r"(a) : "l"(p));
    return a;
}

__device__ __forceinline__ void cpa16(uint32_t dst, const char* src) {
    asm volatile("cp.async.cg.shared.global [%0], [%1], 16;" :: "r"(dst), "l"(src) : "memory");
}
#define CP_COMMIT() asm volatile("cp.async.commit_group;" ::: "memory")
#define CP_WAIT0()  asm volatile("cp.async.wait_group 0;" ::: "memory")
#define CP_WAIT1()  asm volatile("cp.async.wait_group 1;" ::: "memory")

// ldmatrix x4 from a 128B-row SW128 buffer: 16 rows x 16 bf16 cols.
__device__ __forceinline__ void ld4(uint32_t r[4], uint32_t base, int row0, int kbyte) {
    int l = threadIdx.x & 31;
    uint32_t o = (uint32_t)((row0 + (l & 15)) * 128 + kbyte + ((l >> 4) << 4));
    uint32_t a = base + SW(o);
    asm volatile("ldmatrix.sync.aligned.m8n8.x4.shared.b16 {%0,%1,%2,%3}, [%4];"
                 : "=r"(r[0]), "=r"(r[1]), "=r"(r[2]), "=r"(r[3]) : "r"(a));
}

__device__ __forceinline__ void mma16816(float c[4], const uint32_t a[4], uint32_t b0, uint32_t b1) {
    asm volatile(
        "mma.sync.aligned.m16n8k16.row.col.f32.bf16.bf16.f32 "
        "{%0,%1,%2,%3}, {%4,%5,%6,%7}, {%8,%9}, {%0,%1,%2,%3};"
        : "+f"(c[0]), "+f"(c[1]), "+f"(c[2]), "+f"(c[3])
        : "r"(a[0]), "r"(a[1]), "r"(a[2]), "r"(a[3]), "r"(b0), "r"(b1));
}

// ---------------------------------------------------------------------------
// Prep A: split Q/K -> swizzled bf16 gmem images, direct stores (no smem).
// Also zeroes g_denom. grid (64 slabs, N), 128 threads; slab = 64 rows.
// ---------------------------------------------------------------------------
__global__ void __launch_bounds__(128)
prep_qk(const float* __restrict__ Q, const float* __restrict__ K) {
    int tid = threadIdx.x;
    int s = blockIdx.x, n = blockIdx.y;
    int c = s >> 1, half = s & 1;
    size_t gb = (size_t)(n * 32 + c) * 32768;
    const float* Qg = Q + ((size_t)n * HW + s * 64) * CD;
    const float* Kg = K + ((size_t)n * HW + s * 64) * CD;

    if (s < 32) g_denom[n * HW + s * 128 + tid] = 0.0f;

#pragma unroll
    for (int i = 0; i < 8; i++) {
        int lin4 = i * 128 + tid;
        int r  = lin4 >> 4;
        int c4 = (lin4 & 15) * 4;
        unsigned o = (half * 64 + r) * 128 + c4 * 2;
        unsigned sw = SW(o);
        {
            float4 v = *(const float4*)(Qg + r * CD + c4);
            __nv_bfloat162 h0 = __floats2bfloat162_rn(v.x, v.y);
            __nv_bfloat162 h1 = __floats2bfloat162_rn(v.z, v.w);
            __nv_bfloat162 l0 = __floats2bfloat162_rn(v.x - __low2float(h0), v.y - __high2float(h0));
            __nv_bfloat162 l1 = __floats2bfloat162_rn(v.z - __low2float(h1), v.w - __high2float(h1));
            *(unsigned*)(g_Qb + gb + sw)             = *(unsigned*)&h0;
            *(unsigned*)(g_Qb + gb + sw + 4)         = *(unsigned*)&h1;
            *(unsigned*)(g_Qb + gb + 16384 + sw)     = *(unsigned*)&l0;
            *(unsigned*)(g_Qb + gb + 16384 + sw + 4) = *(unsigned*)&l1;
        }
        {
            float4 v = *(const float4*)(Kg + r * CD + c4);
            __nv_bfloat162 h0 = __floats2bfloat162_rn(v.x, v.y);
            __nv_bfloat162 h1 = __floats2bfloat162_rn(v.z, v.w);
            __nv_bfloat162 l0 = __floats2bfloat162_rn(v.x - __low2float(h0), v.y - __high2float(h0));
            __nv_bfloat162 l1 = __floats2bfloat162_rn(v.z - __low2float(h1), v.w - __high2float(h1));
            *(unsigned*)(g_Kb + gb + sw)             = *(unsigned*)&h0;
            *(unsigned*)(g_Kb + gb + sw + 4)         = *(unsigned*)&h1;
            *(unsigned*)(g_Kb + gb + 16384 + sw)     = *(unsigned*)&l0;
            *(unsigned*)(g_Kb + gb + 16384 + sw + 4) = *(unsigned*)&l1;
        }
    }
}

// ---------------------------------------------------------------------------
// Pass 1: denom. CTA = 64 k rows x quarter of q-range, double-buffered Q chunks.
// smem: K 16KB + 2 x Qchunk 16KB = 48KB; 128 threads.
// ILP: ks outer, ntp inner, 8 accumulator groups.
// ---------------------------------------------------------------------------
#define Z1_KHI 0
#define Z1_KLO 8192
#define Z1_BUF(b) (16384 + (b) * 16384)
#define P1_SMEM 49152

__device__ __forceinline__ void p1_issue_q(uint32_t sb, int b, int n, int cc) {
    int tid = threadIdx.x;
    const char* qhi = g_Qb + (size_t)(n * 32 + (cc >> 1)) * 32768 + (cc & 1) * 8192;
    const char* qlo = qhi + 16384;
    uint32_t d = sb + Z1_BUF(b);
#pragma unroll
    for (int i = 0; i < 4; i++) {
        int o = (i * 128 + tid) * 16;
        cpa16(d + o, qhi + o);
        cpa16(d + 8192 + o, qlo + o);
    }
}

__global__ void __launch_bounds__(128, 3)
pass1_denom() {
    extern __shared__ char smem[];
    uint32_t sb = smem_u32(smem);
    int tid = threadIdx.x, w = tid >> 5, l = tid & 31;
    int kt = blockIdx.x;   // 0..63: 64-row k tile
    int qs = blockIdx.y;   // 0..3: q quarter (16 chunks of 64 rows)
    int n  = blockIdx.z;

    {
        const char* khi = g_Kb + (size_t)(n * 32 + (kt >> 1)) * 32768 + (kt & 1) * 8192;
        const char* klo = khi + 16384;
#pragma unroll
        for (int i = 0; i < 4; i++) {
            int o = (i * 128 + tid) * 16;
            cpa16(sb + Z1_KHI + o, khi + o);
            cpa16(sb + Z1_KLO + o, klo + o);
        }
        p1_issue_q(sb, 0, n, qs * 16);
        CP_COMMIT();
    }

    uint32_t ah[4][4], al[4][4];
    float ps0 = 0.f, ps1 = 0.f;

    for (int j = 0; j < 16; j++) {
        int b = j & 1;
        if (j < 15) { p1_issue_q(sb, b ^ 1, n, qs * 16 + j + 1); CP_COMMIT(); CP_WAIT1(); }
        else        { CP_WAIT0(); }
        __syncthreads();

        if (j == 0) {
#pragma unroll
            for (int ks = 0; ks < 4; ks++) {
                ld4(ah[ks], sb + Z1_KHI, w * 16, ks * 32);
                ld4(al[ks], sb + Z1_KLO, w * 16, ks * 32);
            }
        }

        uint32_t qb = sb + Z1_BUF(b);
        float sacc[4][8];
#pragma unroll
        for (int t = 0; t < 4; t++)
#pragma unroll
            for (int u = 0; u < 8; u++) sacc[t][u] = 0.f;

#pragma unroll
        for (int ks = 0; ks < 4; ks++) {
            uint32_t bh[4][4], bl[4][4];
#pragma unroll
            for (int ntp = 0; ntp < 4; ntp++) {
                ld4(bh[ntp], qb, ntp * 16, ks * 32);
                ld4(bl[ntp], qb + 8192, ntp * 16, ks * 32);
            }
            // 8 independent accumulator chains; same-acc reuse distance = 8 MMAs
#pragma unroll
            for (int ntp = 0; ntp < 4; ntp++) mma16816(&sacc[ntp][0], ah[ks], bh[ntp][0], bh[ntp][2]);
#pragma unroll
            for (int ntp = 0; ntp < 4; ntp++) mma16816(&sacc[ntp][4], ah[ks], bh[ntp][1], bh[ntp][3]);
#pragma unroll
            for (int ntp = 0; ntp < 4; ntp++) mma16816(&sacc[ntp][0], ah[ks], bl[ntp][0], bl[ntp][2]);
#pragma unroll
            for (int ntp = 0; ntp < 4; ntp++) mma16816(&sacc[ntp][4], ah[ks], bl[ntp][1], bl[ntp][3]);
#pragma unroll
            for (int ntp = 0; ntp < 4; ntp++) mma16816(&sacc[ntp][0], al[ks], bh[ntp][0], bh[ntp][2]);
#pragma unroll
            for (int ntp = 0; ntp < 4; ntp++) mma16816(&sacc[ntp][4], al[ks], bh[ntp][1], bh[ntp][3]);
        }

#pragma unroll
        for (int ntp = 0; ntp < 4; ntp++) {
            ps0 += __expf(sacc[ntp][0] * SCALE) + __expf(sacc[ntp][1] * SCALE)
                 + __expf(sacc[ntp][4] * SCALE) + __expf(sacc[ntp][5] * SCALE);
            ps1 += __expf(sacc[ntp][2] * SCALE) + __expf(sacc[ntp][3] * SCALE)
                 + __expf(sacc[ntp][6] * SCALE) + __expf(sacc[ntp][7] * SCALE);
        }
        __syncthreads();
    }

    ps0 += __shfl_xor_sync(0xFFFFFFFFu, ps0, 1);
    ps0 += __shfl_xor_sync(0xFFFFFFFFu, ps0, 2);
    ps1 += __shfl_xor_sync(0xFFFFFFFFu, ps1, 1);
    ps1 += __shfl_xor_sync(0xFFFFFFFFu, ps1, 2);
    if ((l & 3) == 0) {
        int r = l >> 2;
        atomicAdd(&g_denom[n * HW + kt * 64 + w * 16 + r],     ps0);
        atomicAdd(&g_denom[n * HW + kt * 64 + w * 16 + 8 + r], ps1);
    }
}

// ---------------------------------------------------------------------------
// Prep B: split Vt (needs denom). grid (64 slabs, N), 128 threads; slab = 64 k rows.
// ---------------------------------------------------------------------------
__global__ void __launch_bounds__(128)
prep_v(const float* __restrict__ V) {
    __shared__ char sm[16384];   // [hi 8KB][lo 8KB] for one k-half
    int tid = threadIdx.x;
    int s = blockIdx.x, n = blockIdx.y;
    int c = s >> 1, h = s & 1;

    const float* g = V + ((size_t)n * HW + s * 64) * CD;
    const float* dn = g_denom + n * HW + s * 64;
#pragma unroll
    for (int i = 0; i < 8; i++) {
        int lin4 = i * 128 + tid;
        int k  = lin4 >> 4;        // local 0..63
        int c4 = (lin4 & 15) * 4;
        float di = __frcp_rn(dn[k]);
        float4 v = *(const float4*)(g + k * CD + c4);
        float vv[4] = {v.x * di, v.y * di, v.z * di, v.w * di};
#pragma unroll
        for (int j = 0; j < 4; j++) {
            __nv_bfloat16 hb = __float2bfloat16_rn(vv[j]);
            __nv_bfloat16 lb = __float2bfloat16_rn(vv[j] - __bfloat162float(hb));
            unsigned o = (c4 + j) * 128 + k * 2;
            unsigned sw = SW(o);
            *(__nv_bfloat16*)(sm + sw) = hb;
            *(__nv_bfloat16*)(sm + 8192 + sw) = lb;
        }
    }
    __syncthreads();

    size_t gbh = (size_t)(n * 32 + c) * 32768 + h * 8192;          // hi half
    size_t gbl = gbh + 16384;                                      // lo half
#pragma unroll
    for (int i = 0; i < 4; i++) {
        int o = (i * 128 + tid) * 16;
        *(float4*)(g_Vb + gbh + o) = *(const float4*)(sm + o);
        *(float4*)(g_Vb + gbl + o) = *(const float4*)(sm + 8192 + o);
    }
}

// ---------------------------------------------------------------------------
// Pass 2: CTA = 64 q rows, 128 threads, 2 CTAs/SM. 64 k-chunks of 64 rows,
// double-buffered K+Vt. ILP: ks outer, tile inner, 8 accumulator groups.
// smem: Q 16KB + 2 x (K 16KB + Vt 16KB) = 80KB.
// ---------------------------------------------------------------------------
#define Q_HI 0
#define Q_LO 8192
#define BUF(b) (16384 + (b) * 32768)   /* KH, KL=+8192, VH=+16384, VL=+24576 */
#define P2_SMEM 81920

__device__ __forceinline__ void p2_issue_kv(uint32_t sb, int b, int n, int cc) {
    int tid = threadIdx.x;
    size_t cb = (size_t)(n * 32 + (cc >> 1)) * 32768 + (cc & 1) * 8192;
    const char* khi = g_Kb + cb;
    const char* vhi = g_Vb + cb;
    uint32_t d = sb + BUF(b);
#pragma unroll
    for (int i = 0; i < 4; i++) {
        int o = (i * 128 + tid) * 16;
        cpa16(d + o,         khi + o);
        cpa16(d + 8192 + o,  khi + 16384 + o);
        cpa16(d + 16384 + o, vhi + o);
        cpa16(d + 24576 + o, vhi + 16384 + o);
    }
}

__global__ void __launch_bounds__(128, 2)
pass2_out(float* __restrict__ Out) {
    extern __shared__ char smem[];
    uint32_t sb = smem_u32(smem);
    int tid = threadIdx.x, w = tid >> 5, l = tid & 31;
    int qt = blockIdx.x, n = blockIdx.y;

    {
        const char* qhi = g_Qb + (size_t)(n * 32 + (qt >> 1)) * 32768 + (qt & 1) * 8192;
        const char* qlo = qhi + 16384;
#pragma unroll
        for (int i = 0; i < 4; i++) {
            int o = (i * 128 + tid) * 16;
            cpa16(sb + Q_HI + o, qhi + o);
            cpa16(sb + Q_LO + o, qlo + o);
        }
        p2_issue_kv(sb, 0, n, 0);
        CP_COMMIT();
    }

    float oacc[8][4];
#pragma unroll
    for (int i = 0; i < 8; i++)
#pragma unroll
        for (int j = 0; j < 4; j++) oacc[i][j] = 0.f;

    uint32_t qh[4][4], ql[4][4];

    for (int cc = 0; cc < 64; cc++) {
        int b = cc & 1;
        if (cc < 63) { p2_issue_kv(sb, b ^ 1, n, cc + 1); CP_COMMIT(); CP_WAIT1(); }
        else         { CP_WAIT0(); }
        __syncthreads();

        if (cc == 0) {
#pragma unroll
            for (int ks = 0; ks < 4; ks++) {
                ld4(qh[ks], sb + Q_HI, w * 16, ks * 32);
                ld4(ql[ks], sb + Q_LO, w * 16, ks * 32);
            }
        }

        uint32_t kb = sb + BUF(b);
        uint32_t vb = kb + 16384;

        // --- S = Q.K^T over 64 k cols, 8 independent accumulator chains ---
        float sacc[4][8];
#pragma unroll
        for (int t = 0; t < 4; t++)
#pragma unroll
            for (int u = 0; u < 8; u++) sacc[t][u] = 0.f;

#pragma unroll
        for (int ks = 0; ks < 4; ks++) {
            uint32_t bh[4][4], bl[4][4];
#pragma unroll
            for (int ntp = 0; ntp < 4; ntp++) {
                ld4(bh[ntp], kb, ntp * 16, ks * 32);
                ld4(bl[ntp], kb + 8192, ntp * 16, ks * 32);
            }
#pragma unroll
            for (int ntp = 0; ntp < 4; ntp++) mma16816(&sacc[ntp][0], qh[ks], bh[ntp][0], bh[ntp][2]);
#pragma unroll
            for (int ntp = 0; ntp < 4; ntp++) mma16816(&sacc[ntp][4], qh[ks], bh[ntp][1], bh[ntp][3]);
#pragma unroll
            for (int ntp = 0; ntp < 4; ntp++) mma16816(&sacc[ntp][0], qh[ks], bl[ntp][0], bl[ntp][2]);
#pragma unroll
            for (int ntp = 0; ntp < 4; ntp++) mma16816(&sacc[ntp][4], qh[ks], bl[ntp][1], bl[ntp][3]);
#pragma unroll
            for (int ntp = 0; ntp < 4; ntp++) mma16816(&sacc[ntp][0], ql[ks], bh[ntp][0], bh[ntp][2]);
#pragma unroll
            for (int ntp = 0; ntp < 4; ntp++) mma16816(&sacc[ntp][4], ql[ks], bh[ntp][1], bh[ntp][3]);
        }

        // --- exp; pack P A-fragments in registers ---
        uint32_t ph[4][4], pl[4][4];
#pragma unroll
        for (int ntp = 0; ntp < 4; ntp++) {
            float e00 = __expf(sacc[ntp][0] * SCALE), e01 = __expf(sacc[ntp][1] * SCALE);
            float e02 = __expf(sacc[ntp][2] * SCALE), e03 = __expf(sacc[ntp][3] * SCALE);
            float e10 = __expf(sacc[ntp][4] * SCALE), e11 = __expf(sacc[ntp][5] * SCALE);
            float e12 = __expf(sacc[ntp][6] * SCALE), e13 = __expf(sacc[ntp][7] * SCALE);
            __nv_bfloat162 h;
            h = __floats2bfloat162_rn(e00, e01); ph[ntp][0] = *(uint32_t*)&h;
            __nv_bfloat162 t0 = __floats2bfloat162_rn(e00 - __low2float(h), e01 - __high2float(h));
            pl[ntp][0] = *(uint32_t*)&t0;
            h = __floats2bfloat162_rn(e02, e03); ph[ntp][1] = *(uint32_t*)&h;
            __nv_bfloat162 t1 = __floats2bfloat162_rn(e02 - __low2float(h), e03 - __high2float(h));
            pl[ntp][1] = *(uint32_t*)&t1;
            h = __floats2bfloat162_rn(e10, e11); ph[ntp][2] = *(uint32_t*)&h;
            __nv_bfloat162 t2 = __floats2bfloat162_rn(e10 - __low2float(h), e11 - __high2float(h));
            pl[ntp][2] = *(uint32_t*)&t2;
            h = __floats2bfloat162_rn(e12, e13); ph[ntp][3] = *(uint32_t*)&h;
            __nv_bfloat162 t3 = __floats2bfloat162_rn(e12 - __low2float(h), e13 - __high2float(h));
            pl[ntp][3] = *(uint32_t*)&t3;
        }

        // --- acc += P . Vt', 8 independent accumulator chains ---
#pragma unroll
        for (int ks = 0; ks < 4; ks++) {
            uint32_t vh[4][4], vl[4][4];
#pragma unroll
            for (int cp = 0; cp < 4; cp++) {
                ld4(vh[cp], vb, cp * 16, ks * 32);
                ld4(vl[cp], vb + 8192, cp * 16, ks * 32);
            }
#pragma unroll
            for (int cp = 0; cp < 4; cp++) mma16816(oacc[2 * cp],     ph[ks], vh[cp][0], vh[cp][2]);
#pragma unroll
            for (int cp = 0; cp < 4; cp++) mma16816(oacc[2 * cp + 1], ph[ks], vh[cp][1], vh[cp][3]);
#pragma unroll
            for (int cp = 0; cp < 4; cp++) mma16816(oacc[2 * cp],     ph[ks], vl[cp][0], vl[cp][2]);
#pragma unroll
            for (int cp = 0; cp < 4; cp++) mma16816(oacc[2 * cp + 1], ph[ks], vl[cp][1], vl[cp][3]);
#pragma unroll
            for (int cp = 0; cp < 4; cp++) mma16816(oacc[2 * cp],     pl[ks], vh[cp][0], vh[cp][2]);
#pragma unroll
            for (int cp = 0; cp < 4; cp++) mma16816(oacc[2 * cp + 1], pl[ks], vh[cp][1], vh[cp][3]);
        }
        __syncthreads();
    }

    {
        int qr = qt * 64 + w * 16 + (l >> 2);
        float* o0 = Out + ((size_t)n * HW + qr) * CD;
        float* o1 = o0 + 8 * CD;
#pragma unroll
        for (int nt = 0; nt < 8; nt++) {
            int c0 = nt * 8 + 2 * (l & 3);
            *(float2*)(o0 + c0) = make_float2(oacc[nt][0], oacc[nt][1]);
            *(float2*)(o1 + c0) = make_float2(oacc[nt][2], oacc[nt][3]);
        }
    }
}

// ---------------------------------------------------------------------------
extern "C" void kernel_launch(void* const* d_in, const int* in_sizes, int n_in,
                              void* d_out, int out_size) {
    const float* Q = (const float*)d_in[0];
    const float* K = (const float*)d_in[1];
    const float* V = (const float*)d_in[2];
    float* Out = (float*)d_out;
    const int N = in_sizes[0] / (HW * CD);  // = 4

    cudaFuncSetAttribute(pass1_denom, cudaFuncAttributeMaxDynamicSharedMemorySize, P1_SMEM);
    cudaFuncSetAttribute(pass2_out,   cudaFuncAttributeMaxDynamicSharedMemorySize, P2_SMEM);

    prep_qk<<<dim3(64, N), 128>>>(Q, K);
    pass1_denom<<<dim3(64, 4, N), 128, P1_SMEM>>>();
    prep_v<<<dim3(64, N), 128>>>(V);
    pass2_out<<<dim3(64, N), 128, P2_SMEM>>>(Out);
}

// round 10
// speedup vs baseline: 4.2910x; 1.4213x over previous
#include <cuda_runtime.h>
#include <cuda_fp16.h>
#include <cstdint>
#include <cstddef>

#define HW 4096
#define CD 64
// SCALE * log2(e): S' = logit*log2e, p = exp2(S')
#define PRESCALE 0.18033688011112042f
#define SW(o) ((o) ^ (((o) >> 3) & 0x70))

// denom[n][k] = sum_q exp(scale * Q[n,q,:].K[n,k,:])
__device__ float g_denom[4 * HW];

// fp16 images (swizzled 128B rows, ready for cp.async -> ldmatrix):
// Q: plain fp16, per (n, 128-row chunk): 16KB.
__device__ char g_Qb[(size_t)4 * 32 * 16384];
// K: prescaled by PRESCALE, split hi/lo: per chunk [hi 16KB][lo 16KB].
__device__ char g_Kb[(size_t)4 * 32 * 32768];
// Vt = (V/denom)^T: per chunk [vh: k-half0 8KB, k-half1 8KB][vl: same].
__device__ char g_Vb[(size_t)4 * 32 * 32768];

__device__ __forceinline__ uint32_t smem_u32(const void* p) {
    uint32_t a;
    asm("{ .reg .u64 t; cvta.to.shared.u64 t, %1; cvt.u32.u64 %0, t; }" : "=r"(a) : "l"(p));
    return a;
}

__device__ __forceinline__ void cpa16(uint32_t dst, const char* src) {
    asm volatile("cp.async.cg.shared.global [%0], [%1], 16;" :: "r"(dst), "l"(src) : "memory");
}
#define CP_COMMIT() asm volatile("cp.async.commit_group;" ::: "memory")
#define CP_WAIT0()  asm volatile("cp.async.wait_group 0;" ::: "memory")

// ldmatrix x4 from a 128B-row SW128 buffer: 16 rows x 16 fp16 cols.
__device__ __forceinline__ void ld4(uint32_t r[4], uint32_t base, int row0, int kbyte) {
    int l = threadIdx.x & 31;
    uint32_t o = (uint32_t)((row0 + (l & 15)) * 128 + kbyte + ((l >> 4) << 4));
    uint32_t a = base + SW(o);
    asm volatile("ldmatrix.sync.aligned.m8n8.x4.shared.b16 {%0,%1,%2,%3}, [%4];"
                 : "=r"(r[0]), "=r"(r[1]), "=r"(r[2]), "=r"(r[3]) : "r"(a));
}

__device__ __forceinline__ void mma16816(float c[4], const uint32_t a[4], uint32_t b0, uint32_t b1) {
    asm volatile(
        "mma.sync.aligned.m16n8k16.row.col.f32.f16.f16.f32 "
        "{%0,%1,%2,%3}, {%4,%5,%6,%7}, {%8,%9}, {%0,%1,%2,%3};"
        : "+f"(c[0]), "+f"(c[1]), "+f"(c[2]), "+f"(c[3])
        : "r"(a[0]), "r"(a[1]), "r"(a[2]), "r"(a[3]), "r"(b0), "r"(b1));
}

// ---------------------------------------------------------------------------
// Prep A: Q -> plain fp16; K -> PRESCALE*K split fp16 hi/lo. Zeroes g_denom.
// grid (64 slabs, N), 128 threads; slab = 64 rows.
// ---------------------------------------------------------------------------
__global__ void __launch_bounds__(128)
prep_qk(const float* __restrict__ Q, const float* __restrict__ K) {
    int tid = threadIdx.x;
    int s = blockIdx.x, n = blockIdx.y;
    int c = s >> 1, half = s & 1;
    size_t qgb = (size_t)(n * 32 + c) * 16384;
    size_t kgb = (size_t)(n * 32 + c) * 32768;
    const float* Qg = Q + ((size_t)n * HW + s * 64) * CD;
    const float* Kg = K + ((size_t)n * HW + s * 64) * CD;

    if (s < 32) g_denom[n * HW + s * 128 + tid] = 0.0f;

#pragma unroll
    for (int i = 0; i < 8; i++) {
        int lin4 = i * 128 + tid;
        int r  = lin4 >> 4;
        int c4 = (lin4 & 15) * 4;
        unsigned o = (half * 64 + r) * 128 + c4 * 2;
        unsigned sw = SW(o);
        {
            float4 v = *(const float4*)(Qg + r * CD + c4);
            __half2 h0 = __floats2half2_rn(v.x, v.y);
            __half2 h1 = __floats2half2_rn(v.z, v.w);
            *(unsigned*)(g_Qb + qgb + sw)     = *(unsigned*)&h0;
            *(unsigned*)(g_Qb + qgb + sw + 4) = *(unsigned*)&h1;
        }
        {
            float4 v = *(const float4*)(Kg + r * CD + c4);
            float x0 = v.x * PRESCALE, x1 = v.y * PRESCALE;
            float x2 = v.z * PRESCALE, x3 = v.w * PRESCALE;
            __half2 h0 = __floats2half2_rn(x0, x1);
            __half2 h1 = __floats2half2_rn(x2, x3);
            __half2 l0 = __floats2half2_rn(x0 - __low2float(h0), x1 - __high2float(h0));
            __half2 l1 = __floats2half2_rn(x2 - __low2float(h1), x3 - __high2float(h1));
            *(unsigned*)(g_Kb + kgb + sw)             = *(unsigned*)&h0;
            *(unsigned*)(g_Kb + kgb + sw + 4)         = *(unsigned*)&h1;
            *(unsigned*)(g_Kb + kgb + 16384 + sw)     = *(unsigned*)&l0;
            *(unsigned*)(g_Kb + kgb + 16384 + sw + 4) = *(unsigned*)&l1;
        }
    }
}

// ---------------------------------------------------------------------------
// Pass 1: denom. CTA = 64 k rows x quarter of q-range.
// A = K hi/lo (chunk-invariant frags), B = Q fp16 chunks (8KB, double-buffered).
// smem: KH 8KB + KL 8KB + 2 x Qbuf 8KB = 32KB; 128 threads, up to 4 CTAs/SM.
// ---------------------------------------------------------------------------
#define Z1_KH 0
#define Z1_KL 8192
#define Z1_QB(b) (16384 + (b) * 8192)
#define P1_SMEM 32768

__device__ __forceinline__ void p1_issue_q(uint32_t sb, int b, int n, int cc) {
    int tid = threadIdx.x;
    const char* qs = g_Qb + (size_t)(n * 32 + (cc >> 1)) * 16384 + (cc & 1) * 8192;
    uint32_t d = sb + Z1_QB(b);
#pragma unroll
    for (int i = 0; i < 4; i++) {
        int o = (i * 128 + tid) * 16;
        cpa16(d + o, qs + o);
    }
}

__global__ void __launch_bounds__(128, 4)
pass1_denom() {
    extern __shared__ char smem[];
    uint32_t sb = smem_u32(smem);
    int tid = threadIdx.x, w = tid >> 5, l = tid & 31;
    int kt = blockIdx.x;   // 0..63: 64-row k tile
    int qs = blockIdx.y;   // 0..3: q quarter (16 chunks of 64 rows)
    int n  = blockIdx.z;

    {
        const char* khi = g_Kb + (size_t)(n * 32 + (kt >> 1)) * 32768 + (kt & 1) * 8192;
        const char* klo = khi + 16384;
#pragma unroll
        for (int i = 0; i < 4; i++) {
            int o = (i * 128 + tid) * 16;
            cpa16(sb + Z1_KH + o, khi + o);
            cpa16(sb + Z1_KL + o, klo + o);
        }
        p1_issue_q(sb, 0, n, qs * 16);
        CP_COMMIT();
    }

    uint32_t ah[4][4], al[4][4];
    float ps0 = 0.f, ps1 = 0.f;

    for (int j = 0; j < 16; j++) {
        int b = j & 1;
        CP_WAIT0();
        __syncthreads();
        if (j < 15) { p1_issue_q(sb, b ^ 1, n, qs * 16 + j + 1); CP_COMMIT(); }
        if (j == 0) {
#pragma unroll
            for (int ks = 0; ks < 4; ks++) {
                ld4(ah[ks], sb + Z1_KH, w * 16, ks * 32);
                ld4(al[ks], sb + Z1_KL, w * 16, ks * 32);
            }
        }

        uint32_t qb = sb + Z1_QB(b);
        float sacc[4][8];
#pragma unroll
        for (int t = 0; t < 4; t++)
#pragma unroll
            for (int u = 0; u < 8; u++) sacc[t][u] = 0.f;

#pragma unroll
        for (int ks = 0; ks < 4; ks++) {
            uint32_t bh[4][4];
#pragma unroll
            for (int ntp = 0; ntp < 4; ntp++) ld4(bh[ntp], qb, ntp * 16, ks * 32);
#pragma unroll
            for (int ntp = 0; ntp < 4; ntp++) mma16816(&sacc[ntp][0], ah[ks], bh[ntp][0], bh[ntp][2]);
#pragma unroll
            for (int ntp = 0; ntp < 4; ntp++) mma16816(&sacc[ntp][4], ah[ks], bh[ntp][1], bh[ntp][3]);
#pragma unroll
            for (int ntp = 0; ntp < 4; ntp++) mma16816(&sacc[ntp][0], al[ks], bh[ntp][0], bh[ntp][2]);
#pragma unroll
            for (int ntp = 0; ntp < 4; ntp++) mma16816(&sacc[ntp][4], al[ks], bh[ntp][1], bh[ntp][3]);
        }

#pragma unroll
        for (int ntp = 0; ntp < 4; ntp++) {
            ps0 += exp2f(sacc[ntp][0]) + exp2f(sacc[ntp][1])
                 + exp2f(sacc[ntp][4]) + exp2f(sacc[ntp][5]);
            ps1 += exp2f(sacc[ntp][2]) + exp2f(sacc[ntp][3])
                 + exp2f(sacc[ntp][6]) + exp2f(sacc[ntp][7]);
        }
    }

    ps0 += __shfl_xor_sync(0xFFFFFFFFu, ps0, 1);
    ps0 += __shfl_xor_sync(0xFFFFFFFFu, ps0, 2);
    ps1 += __shfl_xor_sync(0xFFFFFFFFu, ps1, 1);
    ps1 += __shfl_xor_sync(0xFFFFFFFFu, ps1, 2);
    if ((l & 3) == 0) {
        int r = l >> 2;
        atomicAdd(&g_denom[n * HW + kt * 64 + w * 16 + r],     ps0);
        atomicAdd(&g_denom[n * HW + kt * 64 + w * 16 + 8 + r], ps1);
    }
}

// ---------------------------------------------------------------------------
// Prep B: Vt = (V/denom)^T, fp16 split hi/lo. grid (64 slabs, N), 128 thr.
// ---------------------------------------------------------------------------
__global__ void __launch_bounds__(128)
prep_v(const float* __restrict__ V) {
    __shared__ char sm[16384];   // [hi 8KB][lo 8KB] for one 64-k half
    int tid = threadIdx.x;
    int s = blockIdx.x, n = blockIdx.y;
    int c = s >> 1, h = s & 1;

    const float* g = V + ((size_t)n * HW + s * 64) * CD;
    const float* dn = g_denom + n * HW + s * 64;
#pragma unroll
    for (int i = 0; i < 8; i++) {
        int lin4 = i * 128 + tid;
        int k  = lin4 >> 4;        // local 0..63
        int c4 = (lin4 & 15) * 4;
        float di = __frcp_rn(dn[k]);
        float4 v = *(const float4*)(g + k * CD + c4);
        float vv[4] = {v.x * di, v.y * di, v.z * di, v.w * di};
#pragma unroll
        for (int j = 0; j < 4; j++) {
            __half hb = __float2half_rn(vv[j]);
            __half lb = __float2half_rn(vv[j] - __half2float(hb));
            unsigned o = (c4 + j) * 128 + k * 2;
            unsigned sw = SW(o);
            *(__half*)(sm + sw) = hb;
            *(__half*)(sm + 8192 + sw) = lb;
        }
    }
    __syncthreads();

    size_t gbh = (size_t)(n * 32 + c) * 32768 + h * 8192;
    size_t gbl = gbh + 16384;
#pragma unroll
    for (int i = 0; i < 4; i++) {
        int o = (i * 128 + tid) * 16;
        *(float4*)(g_Vb + gbh + o) = *(const float4*)(sm + o);
        *(float4*)(g_Vb + gbl + o) = *(const float4*)(sm + 8192 + o);
    }
}

// ---------------------------------------------------------------------------
// Pass 2: CTA = 64 q rows, 128 threads, 3 CTAs/SM. 64 k-chunks of 64 rows,
// double-buffered K+Vt. fp16 2-term: S = q.(kh+kl); PV = p.(vh+vl).
// smem: Q 8KB + 2 x 32KB = 72KB.
// ---------------------------------------------------------------------------
#define Q_OFF 0
#define BUF(b) (8192 + (b) * 32768)   /* KH, KL=+8192, VH=+16384, VL=+24576 */
#define P2_SMEM 73728

__device__ __forceinline__ void p2_issue_kv(uint32_t sb, int b, int n, int cc) {
    int tid = threadIdx.x;
    size_t cb = (size_t)(n * 32 + (cc >> 1)) * 32768 + (cc & 1) * 8192;
    const char* khi = g_Kb + cb;
    const char* vhi = g_Vb + cb;
    uint32_t d = sb + BUF(b);
#pragma unroll
    for (int i = 0; i < 4; i++) {
        int o = (i * 128 + tid) * 16;
        cpa16(d + o,         khi + o);
        cpa16(d + 8192 + o,  khi + 16384 + o);
        cpa16(d + 16384 + o, vhi + o);
        cpa16(d + 24576 + o, vhi + 16384 + o);
    }
}

__global__ void __launch_bounds__(128, 3)
pass2_out(float* __restrict__ Out) {
    extern __shared__ char smem[];
    uint32_t sb = smem_u32(smem);
    int tid = threadIdx.x, w = tid >> 5, l = tid & 31;
    int qt = blockIdx.x, n = blockIdx.y;

    {
        const char* qsrc = g_Qb + (size_t)(n * 32 + (qt >> 1)) * 16384 + (qt & 1) * 8192;
#pragma unroll
        for (int i = 0; i < 4; i++) {
            int o = (i * 128 + tid) * 16;
            cpa16(sb + Q_OFF + o, qsrc + o);
        }
        p2_issue_kv(sb, 0, n, 0);
        CP_COMMIT();
    }

    float oacc[8][4];
#pragma unroll
    for (int i = 0; i < 8; i++)
#pragma unroll
        for (int j = 0; j < 4; j++) oacc[i][j] = 0.f;

    uint32_t qh[4][4];

    for (int cc = 0; cc < 64; cc++) {
        int b = cc & 1;
        CP_WAIT0();
        __syncthreads();
        if (cc < 63) { p2_issue_kv(sb, b ^ 1, n, cc + 1); CP_COMMIT(); }
        if (cc == 0) {
#pragma unroll
            for (int ks = 0; ks < 4; ks++) ld4(qh[ks], sb + Q_OFF, w * 16, ks * 32);
        }

        uint32_t kb = sb + BUF(b);
        uint32_t vb = kb + 16384;

        // --- S' = Q.(Kh + Kl)^T over 64 k cols (logits*log2e) ---
        float sacc[4][8];
#pragma unroll
        for (int t = 0; t < 4; t++)
#pragma unroll
            for (int u = 0; u < 8; u++) sacc[t][u] = 0.f;

#pragma unroll
        for (int ks = 0; ks < 4; ks++) {
            uint32_t bh[4][4], bl[4][4];
#pragma unroll
            for (int ntp = 0; ntp < 4; ntp++) {
                ld4(bh[ntp], kb, ntp * 16, ks * 32);
                ld4(bl[ntp], kb + 8192, ntp * 16, ks * 32);
            }
#pragma unroll
            for (int ntp = 0; ntp < 4; ntp++) mma16816(&sacc[ntp][0], qh[ks], bh[ntp][0], bh[ntp][2]);
#pragma unroll
            for (int ntp = 0; ntp < 4; ntp++) mma16816(&sacc[ntp][4], qh[ks], bh[ntp][1], bh[ntp][3]);
#pragma unroll
            for (int ntp = 0; ntp < 4; ntp++) mma16816(&sacc[ntp][0], qh[ks], bl[ntp][0], bl[ntp][2]);
#pragma unroll
            for (int ntp = 0; ntp < 4; ntp++) mma16816(&sacc[ntp][4], qh[ks], bl[ntp][1], bl[ntp][3]);
        }

        // --- P = exp2(S') as fp16 A-fragments ---
        uint32_t ph[4][4];
#pragma unroll
        for (int ntp = 0; ntp < 4; ntp++) {
            __half2 h;
            h = __floats2half2_rn(exp2f(sacc[ntp][0]), exp2f(sacc[ntp][1])); ph[ntp][0] = *(uint32_t*)&h;
            h = __floats2half2_rn(exp2f(sacc[ntp][2]), exp2f(sacc[ntp][3])); ph[ntp][1] = *(uint32_t*)&h;
            h = __floats2half2_rn(exp2f(sacc[ntp][4]), exp2f(sacc[ntp][5])); ph[ntp][2] = *(uint32_t*)&h;
            h = __floats2half2_rn(exp2f(sacc[ntp][6]), exp2f(sacc[ntp][7])); ph[ntp][3] = *(uint32_t*)&h;
        }

        // --- acc += P.(Vh + Vl)' ---
#pragma unroll
        for (int ks = 0; ks < 4; ks++) {
            uint32_t vh[4][4], vl[4][4];
#pragma unroll
            for (int cp = 0; cp < 4; cp++) {
                ld4(vh[cp], vb, cp * 16, ks * 32);
                ld4(vl[cp], vb + 8192, cp * 16, ks * 32);
            }
#pragma unroll
            for (int cp = 0; cp < 4; cp++) mma16816(oacc[2 * cp],     ph[ks], vh[cp][0], vh[cp][2]);
#pragma unroll
            for (int cp = 0; cp < 4; cp++) mma16816(oacc[2 * cp + 1], ph[ks], vh[cp][1], vh[cp][3]);
#pragma unroll
            for (int cp = 0; cp < 4; cp++) mma16816(oacc[2 * cp],     ph[ks], vl[cp][0], vl[cp][2]);
#pragma unroll
            for (int cp = 0; cp < 4; cp++) mma16816(oacc[2 * cp + 1], ph[ks], vl[cp][1], vl[cp][3]);
        }
    }

    {
        int qr = qt * 64 + w * 16 + (l >> 2);
        float* o0 = Out + ((size_t)n * HW + qr) * CD;
        float* o1 = o0 + 8 * CD;
#pragma unroll
        for (int nt = 0; nt < 8; nt++) {
            int c0 = nt * 8 + 2 * (l & 3);
            *(float2*)(o0 + c0) = make_float2(oacc[nt][0], oacc[nt][1]);
            *(float2*)(o1 + c0) = make_float2(oacc[nt][2], oacc[nt][3]);
        }
    }
}

// ---------------------------------------------------------------------------
extern "C" void kernel_launch(void* const* d_in, const int* in_sizes, int n_in,
                              void* d_out, int out_size) {
    const float* Q = (const float*)d_in[0];
    const float* K = (const float*)d_in[1];
    const float* V = (const float*)d_in[2];
    float* Out = (float*)d_out;
    const int N = in_sizes[0] / (HW * CD);  // = 4

    cudaFuncSetAttribute(pass1_denom, cudaFuncAttributeMaxDynamicSharedMemorySize, P1_SMEM);
    cudaFuncSetAttribute(pass2_out,   cudaFuncAttributeMaxDynamicSharedMemorySize, P2_SMEM);

    prep_qk<<<dim3(64, N), 128>>>(Q, K);
    pass1_denom<<<dim3(64, 4, N), 128, P1_SMEM>>>();
    prep_v<<<dim3(64, N), 128>>>(V);
    pass2_out<<<dim3(64, N), 128, P2_SMEM>>>(Out);
}